// round 9
// baseline (speedup 1.0000x reference)
#include <cuda_runtime.h>
#include <math.h>

#define BB 4
#define NN 1024
#define FF 512
#define EE 32
#define HH 8
#define HD 64
#define MM (BB*NN)   // 4096

// ---- scratch (static device globals: allowed; runtime alloc is not) ----
__device__ unsigned g_Qh[MM*FF], g_Ql[MM*FF];
__device__ unsigned g_Kh[MM*FF], g_Kl[MM*FF];
__device__ unsigned g_Vh[MM*FF], g_Vl[MM*FF];
__device__ unsigned g_AOh[MM*FF], g_AOl[MM*FF];
__device__ unsigned g_xh[MM*FF], g_xl[MM*FF];
__device__ unsigned g_Wqh[FF*FF], g_Wql[FF*FF];
__device__ unsigned g_Wkh[FF*FF], g_Wkl[FF*FF];
__device__ unsigned g_Wvh[FF*FF], g_Wvl[FF*FF];
__device__ unsigned g_Woh[FF*FF], g_Wol[FF*FF];
__device__ float    g_bias[(size_t)BB*HH*NN*NN];   // [b][h][q][k], mask folded in

// ============================================================================
// helpers
// ============================================================================
__device__ __forceinline__ void split_tf32(float x, unsigned& hi, unsigned& lo) {
    asm("cvt.rna.tf32.f32 %0, %1;" : "=r"(hi) : "f"(x));
    float r = x - __uint_as_float(hi);
    asm("cvt.rna.tf32.f32 %0, %1;" : "=r"(lo) : "f"(r));
}

__device__ __forceinline__ void mma_tf32(float (&d)[4], const unsigned (&a)[4],
                                         unsigned b0, unsigned b1) {
    asm volatile(
        "mma.sync.aligned.m16n8k8.row.col.f32.tf32.tf32.f32 "
        "{%0,%1,%2,%3}, {%4,%5,%6,%7}, {%8,%9}, {%0,%1,%2,%3};\n"
        : "+f"(d[0]), "+f"(d[1]), "+f"(d[2]), "+f"(d[3])
        : "r"(a[0]), "r"(a[1]), "r"(a[2]), "r"(a[3]), "r"(b0), "r"(b1));
}

__device__ __forceinline__ unsigned long long pk2(float x, float y) {
    unsigned long long r;
    asm("mov.b64 %0, {%1,%2};" : "=l"(r) : "f"(x), "f"(y));
    return r;
}
__device__ __forceinline__ float2 upk2(unsigned long long v) {
    float x, y;
    asm("mov.b64 {%0,%1}, %2;" : "=f"(x), "=f"(y) : "l"(v));
    return make_float2(x, y);
}
__device__ __forceinline__ unsigned long long fma2(unsigned long long a,
                                                   unsigned long long b,
                                                   unsigned long long c) {
    unsigned long long d;
    asm("fma.rn.f32x2 %0, %1, %2, %3;" : "=l"(d) : "l"(a), "l"(b), "l"(c));
    return d;
}

// ============================================================================
// one-time tf32 split of an fp32 array
// ============================================================================
__global__ __launch_bounds__(256) void split_kernel(
    const float4* __restrict__ src, uint4* __restrict__ H, uint4* __restrict__ L)
{
    const int i = blockIdx.x * 256 + threadIdx.x;
    float4 v = src[i];
    uint4 h, l;
    split_tf32(v.x, h.x, l.x); split_tf32(v.y, h.y, l.y);
    split_tf32(v.z, h.z, l.z); split_tf32(v.w, h.w, l.w);
    H[i] = h; L[i] = l;
}

// ============================================================================
// Pre-split 3xTF32 GEMM (NT): C[M,512] = A[M,512] @ W[512,512]^T + bias.
// BM=BN=64, BK=32, 128 threads = 4 warps (2m x 2n), warp tile 32x32.
// Inner loop: pure LDS + HMMA (operands pre-split to tf32 hi/lo).
// mode 0 (QKV): writes tf32 (hi,lo) outputs; z==0 (Q) pre-scaled 0.125.
// mode 1 (O):   writes float C.
// ============================================================================
__global__ __launch_bounds__(128, 4) void gemm_ps(
    const unsigned* __restrict__ Ah, const unsigned* __restrict__ Al,
    const unsigned* __restrict__ Bh0, const unsigned* __restrict__ Bl0,
    const unsigned* __restrict__ Bh1, const unsigned* __restrict__ Bl1,
    const unsigned* __restrict__ Bh2, const unsigned* __restrict__ Bl2,
    const float* __restrict__ b0p, const float* __restrict__ b1p, const float* __restrict__ b2p,
    float* __restrict__ C,
    unsigned* __restrict__ H0, unsigned* __restrict__ L0,
    unsigned* __restrict__ H1, unsigned* __restrict__ L1,
    unsigned* __restrict__ H2, unsigned* __restrict__ L2,
    int mode)
{
    const unsigned* Bh  = (blockIdx.z == 0) ? Bh0 : (blockIdx.z == 1) ? Bh1 : Bh2;
    const unsigned* Bl  = (blockIdx.z == 0) ? Bl0 : (blockIdx.z == 1) ? Bl1 : Bl2;
    const float*   bias = (blockIdx.z == 0) ? b0p : (blockIdx.z == 1) ? b1p : b2p;

    __shared__ unsigned sAh[64][36], sAl[64][36];
    __shared__ unsigned sBh[64][36], sBl[64][36];

    const int tid  = threadIdx.x;
    const int lane = tid & 31;
    const int wid  = tid >> 5;
    const int gID  = lane >> 2;
    const int tIG  = lane & 3;
    const int wm   = (wid >> 1) * 32;
    const int wn   = (wid & 1) * 32;
    const int m0   = blockIdx.y * 64;
    const int n0   = blockIdx.x * 64;

    float d[2][4][4];
#pragma unroll
    for (int mi = 0; mi < 2; ++mi)
#pragma unroll
        for (int ni = 0; ni < 4; ++ni)
#pragma unroll
            for (int r = 0; r < 4; ++r) d[mi][ni][r] = 0.f;

    for (int k0 = 0; k0 < 512; k0 += 32) {
#pragma unroll
        for (int i = 0; i < 4; ++i) {
            int j = tid + i * 128;
            int row = j >> 3, c = (j & 7) * 4;
            size_t ga = (size_t)(m0 + row) * 512 + k0 + c;
            size_t gb = (size_t)(n0 + row) * 512 + k0 + c;
            *(uint4*)&sAh[row][c] = *(const uint4*)(Ah + ga);
            *(uint4*)&sAl[row][c] = *(const uint4*)(Al + ga);
            *(uint4*)&sBh[row][c] = *(const uint4*)(Bh + gb);
            *(uint4*)&sBl[row][c] = *(const uint4*)(Bl + gb);
        }
        __syncthreads();

#pragma unroll
        for (int ks = 0; ks < 4; ++ks) {
            unsigned bh[4][2], bl[4][2];
#pragma unroll
            for (int ni = 0; ni < 4; ++ni) {
                const int rn = wn + ni * 8 + gID;
                bh[ni][0] = sBh[rn][ks * 8 + tIG];
                bh[ni][1] = sBh[rn][ks * 8 + tIG + 4];
                bl[ni][0] = sBl[rn][ks * 8 + tIG];
                bl[ni][1] = sBl[rn][ks * 8 + tIG + 4];
            }
#pragma unroll
            for (int mi = 0; mi < 2; ++mi) {
                const int ra = wm + mi * 16 + gID;
                unsigned ah[4], al[4];
                ah[0] = sAh[ra    ][ks * 8 + tIG];
                ah[1] = sAh[ra + 8][ks * 8 + tIG];
                ah[2] = sAh[ra    ][ks * 8 + tIG + 4];
                ah[3] = sAh[ra + 8][ks * 8 + tIG + 4];
                al[0] = sAl[ra    ][ks * 8 + tIG];
                al[1] = sAl[ra + 8][ks * 8 + tIG];
                al[2] = sAl[ra    ][ks * 8 + tIG + 4];
                al[3] = sAl[ra + 8][ks * 8 + tIG + 4];
#pragma unroll
                for (int ni = 0; ni < 4; ++ni) {
                    mma_tf32(d[mi][ni], ah, bh[ni][0], bh[ni][1]);
                    mma_tf32(d[mi][ni], ah, bl[ni][0], bl[ni][1]);
                    mma_tf32(d[mi][ni], al, bh[ni][0], bh[ni][1]);
                }
            }
        }
        __syncthreads();
    }

    if (mode == 1) {
#pragma unroll
        for (int mi = 0; mi < 2; ++mi) {
#pragma unroll
            for (int ni = 0; ni < 4; ++ni) {
                const int row = m0 + wm + mi * 16 + gID;
                const int col = n0 + wn + ni * 8 + 2 * tIG;
                float2 bb = *(const float2*)&bias[col];
                *(float2*)&C[(size_t)row * 512 + col] =
                    make_float2(d[mi][ni][0] + bb.x, d[mi][ni][1] + bb.y);
                *(float2*)&C[(size_t)(row + 8) * 512 + col] =
                    make_float2(d[mi][ni][2] + bb.x, d[mi][ni][3] + bb.y);
            }
        }
    } else {
        unsigned* H = (blockIdx.z == 0) ? H0 : (blockIdx.z == 1) ? H1 : H2;
        unsigned* L = (blockIdx.z == 0) ? L0 : (blockIdx.z == 1) ? L1 : L2;
        const float scale = (blockIdx.z == 0) ? 0.125f : 1.0f;  // fold 1/sqrt(HD) into Q
#pragma unroll
        for (int mi = 0; mi < 2; ++mi) {
#pragma unroll
            for (int ni = 0; ni < 4; ++ni) {
                const int row = m0 + wm + mi * 16 + gID;
                const int col = n0 + wn + ni * 8 + 2 * tIG;
                float2 bb = *(const float2*)&bias[col];
                float v00 = (d[mi][ni][0] + bb.x) * scale;
                float v01 = (d[mi][ni][1] + bb.y) * scale;
                float v10 = (d[mi][ni][2] + bb.x) * scale;
                float v11 = (d[mi][ni][3] + bb.y) * scale;
                uint2 h0, l0, h1, l1;
                split_tf32(v00, h0.x, l0.x); split_tf32(v01, h0.y, l0.y);
                split_tf32(v10, h1.x, l1.x); split_tf32(v11, h1.y, l1.y);
                *(uint2*)&H[(size_t)row * 512 + col]       = h0;
                *(uint2*)&L[(size_t)row * 512 + col]       = l0;
                *(uint2*)&H[(size_t)(row + 8) * 512 + col] = h1;
                *(uint2*)&L[(size_t)(row + 8) * 512 + col] = l1;
            }
        }
    }
}

// ============================================================================
// Edge bias (coalesced, smem-staged) — validated R6/R7.
// ============================================================================
__global__ __launch_bounds__(256) void edge_bias_kernel(
    const float4* __restrict__ ef4, const int* __restrict__ mask,
    const float* __restrict__ We, const float* __restrict__ be,
    float* __restrict__ bias)
{
    __shared__ float sE[256 * 33];
    __shared__ unsigned long long sW2[EE][4];
    __shared__ float sbe[HH];

    const int t = threadIdx.x;
    if (t < EE * 4) {
        int e = t >> 2, p = t & 3;
        sW2[e][p] = pk2(We[(2 * p) * EE + e], We[(2 * p + 1) * EE + e]);
    }
    if (t < HH) sbe[t] = be[t];

    const size_t row0 = (size_t)blockIdx.x * 256;
    const size_t base4 = row0 * 8;

#pragma unroll
    for (int i = 0; i < 8; ++i) {
        int j = t + i * 256;
        float4 v = ef4[base4 + j];
        float* dst = &sE[(j >> 3) * 33 + (j & 7) * 4];
        dst[0] = v.x; dst[1] = v.y; dst[2] = v.z; dst[3] = v.w;
    }
    __syncthreads();

    const int mk = mask[row0 + t];

    unsigned long long acc[4];
#pragma unroll
    for (int p = 0; p < 4; ++p) acc[p] = pk2(sbe[2 * p], sbe[2 * p + 1]);

    const float* myrow = &sE[t * 33];
#pragma unroll
    for (int e = 0; e < EE; ++e) {
        float v = myrow[e];
        unsigned long long v2 = pk2(v, v);
#pragma unroll
        for (int p = 0; p < 4; ++p) acc[p] = fma2(v2, sW2[e][p], acc[p]);
    }

    const size_t kq = row0 + t;
    const int k = (int)(kq & (NN - 1));
    const size_t bq = kq >> 10;
    const int q = (int)(bq & (NN - 1));
    const int b = (int)(bq >> 10);

#pragma unroll
    for (int p = 0; p < 4; ++p) {
        float2 o = upk2(acc[p]);
        float o0 = mk ? o.x : -1e30f;
        float o1 = mk ? o.y : -1e30f;
        bias[(((size_t)b * HH + 2 * p    ) * NN + q) * NN + k] = o0;
        bias[(((size_t)b * HH + 2 * p + 1) * NN + q) * NN + k] = o1;
    }
}

// ============================================================================
// Flash attention, 3xTF32 mma with pre-split operands (R8 structure).
// Epilogue now writes AO pre-split (hi/lo) for the O-projection.
// ============================================================================
#define KTILE 32
#define KST 68
#define PST 36
#define SMEM_ATTN ((2*KTILE*KST + 4*64*PST) * 4)   // 54272 bytes

__global__ __launch_bounds__(128, 3) void attn_mma(
    const unsigned* __restrict__ Qh, const unsigned* __restrict__ Ql,
    const unsigned* __restrict__ Kh, const unsigned* __restrict__ Kl,
    const unsigned* __restrict__ Vh, const unsigned* __restrict__ Vl,
    const float* __restrict__ bias,
    unsigned* __restrict__ AOh, unsigned* __restrict__ AOl)
{
    extern __shared__ unsigned smu[];
    unsigned* sKh = smu;                    // [32][KST]
    unsigned* sKl = sKh + KTILE * KST;
    unsigned* sVh = sKl + KTILE * KST;      // Vt: [64 d][PST]
    unsigned* sVl = sVh + 64 * PST;
    unsigned* sPh = sVl + 64 * PST;         // P: [64 q][PST]
    unsigned* sPl = sPh + 64 * PST;

    const int tid  = threadIdx.x;
    const int lane = tid & 31;
    const int wid  = tid >> 5;
    const int gID  = lane >> 2;
    const int tIG  = lane & 3;
    const int wq   = wid * 16;
    const int q0   = blockIdx.x * 64;
    const int h    = blockIdx.y;
    const int b    = blockIdx.z;

    const int rowA = wq + gID;
    const int rowB = wq + gID + 8;

    // ---- Q fragments in registers (Q pre-scaled & pre-split) ----
    unsigned qh[8][4], ql[8][4];
    {
        const size_t rA = (size_t)(b * NN + q0 + rowA) * FF + h * HD;
        const size_t rB = (size_t)(b * NN + q0 + rowB) * FF + h * HD;
#pragma unroll
        for (int ks = 0; ks < 8; ++ks) {
            const int c = ks * 8 + tIG;
            qh[ks][0] = Qh[rA + c];     qh[ks][1] = Qh[rB + c];
            qh[ks][2] = Qh[rA + c + 4]; qh[ks][3] = Qh[rB + c + 4];
            ql[ks][0] = Ql[rA + c];     ql[ks][1] = Ql[rB + c];
            ql[ks][2] = Ql[rA + c + 4]; ql[ks][3] = Ql[rB + c + 4];
        }
    }

    const float* biasb = bias + ((size_t)b * HH + h) * NN * NN;

    float m0 = -1e38f, m1 = -1e38f, l0 = 0.f, l1 = 0.f;
    float oacc[8][4];
#pragma unroll
    for (int ni = 0; ni < 8; ++ni)
#pragma unroll
        for (int r = 0; r < 4; ++r) oacc[ni][r] = 0.f;

    const int lr  = tid >> 2;          // 0..31 load row
    const int lc0 = (tid & 3) * 16;    // load col base

    for (int kt = 0; kt < NN; kt += KTILE) {
        __syncthreads();
        // ---- load K tile [key][d] hi/lo, V tile transposed [d][key] hi/lo ----
        {
            const size_t go = (size_t)(b * NN + kt + lr) * FF + h * HD + lc0;
#pragma unroll
            for (int u = 0; u < 4; ++u) {
                *(uint4*)&sKh[lr * KST + lc0 + 4 * u] = *(const uint4*)(Kh + go + 4 * u);
                *(uint4*)&sKl[lr * KST + lc0 + 4 * u] = *(const uint4*)(Kl + go + 4 * u);
            }
            unsigned th[16], tl[16];
#pragma unroll
            for (int u = 0; u < 4; ++u) {
                *(uint4*)&th[4 * u] = *(const uint4*)(Vh + go + 4 * u);
                *(uint4*)&tl[4 * u] = *(const uint4*)(Vl + go + 4 * u);
            }
#pragma unroll
            for (int cc = 0; cc < 16; ++cc) {
                sVh[(lc0 + cc) * PST + lr] = th[cc];
                sVl[(lc0 + cc) * PST + lr] = tl[cc];
            }
        }
        __syncthreads();

        // ---- S = Q K^T ----
        float sacc[4][4];
#pragma unroll
        for (int ni = 0; ni < 4; ++ni)
#pragma unroll
            for (int r = 0; r < 4; ++r) sacc[ni][r] = 0.f;

#pragma unroll
        for (int ks = 0; ks < 8; ++ks) {
#pragma unroll
            for (int ni = 0; ni < 4; ++ni) {
                const int broff = (ni * 8 + gID) * KST + ks * 8 + tIG;
                unsigned bh0 = sKh[broff], bh1 = sKh[broff + 4];
                unsigned bl0 = sKl[broff], bl1 = sKl[broff + 4];
                mma_tf32(sacc[ni], qh[ks], bh0, bh1);
                mma_tf32(sacc[ni], qh[ks], bl0, bl1);
                mma_tf32(sacc[ni], ql[ks], bh0, bh1);
            }
        }

        // ---- bias + online softmax ----
        const float* br0 = biasb + (size_t)(q0 + rowA) * NN + kt;
        const float* br1 = biasb + (size_t)(q0 + rowB) * NN + kt;
        float mx0 = -1e38f, mx1 = -1e38f;
#pragma unroll
        for (int ni = 0; ni < 4; ++ni) {
            float2 b0v = *(const float2*)&br0[ni * 8 + 2 * tIG];
            float2 b1v = *(const float2*)&br1[ni * 8 + 2 * tIG];
            sacc[ni][0] += b0v.x;
            sacc[ni][1] += b0v.y;
            sacc[ni][2] += b1v.x;
            sacc[ni][3] += b1v.y;
            mx0 = fmaxf(mx0, fmaxf(sacc[ni][0], sacc[ni][1]));
            mx1 = fmaxf(mx1, fmaxf(sacc[ni][2], sacc[ni][3]));
        }
        mx0 = fmaxf(mx0, __shfl_xor_sync(0xffffffffu, mx0, 1));
        mx0 = fmaxf(mx0, __shfl_xor_sync(0xffffffffu, mx0, 2));
        mx1 = fmaxf(mx1, __shfl_xor_sync(0xffffffffu, mx1, 1));
        mx1 = fmaxf(mx1, __shfl_xor_sync(0xffffffffu, mx1, 2));

        const float mn0 = fmaxf(m0, mx0), mn1 = fmaxf(m1, mx1);
        const float c0f = __expf(m0 - mn0), c1f = __expf(m1 - mn1);
        m0 = mn0; m1 = mn1;

        float ps0 = 0.f, ps1 = 0.f;
#pragma unroll
        for (int ni = 0; ni < 4; ++ni) {
            sacc[ni][0] = __expf(sacc[ni][0] - mn0); ps0 += sacc[ni][0];
            sacc[ni][1] = __expf(sacc[ni][1] - mn0); ps0 += sacc[ni][1];
            sacc[ni][2] = __expf(sacc[ni][2] - mn1); ps1 += sacc[ni][2];
            sacc[ni][3] = __expf(sacc[ni][3] - mn1); ps1 += sacc[ni][3];
        }
        ps0 += __shfl_xor_sync(0xffffffffu, ps0, 1);
        ps0 += __shfl_xor_sync(0xffffffffu, ps0, 2);
        ps1 += __shfl_xor_sync(0xffffffffu, ps1, 1);
        ps1 += __shfl_xor_sync(0xffffffffu, ps1, 2);
        l0 = l0 * c0f + ps0;
        l1 = l1 * c1f + ps1;

#pragma unroll
        for (int ni = 0; ni < 8; ++ni) {
            oacc[ni][0] *= c0f; oacc[ni][1] *= c0f;
            oacc[ni][2] *= c1f; oacc[ni][3] *= c1f;
        }

        // ---- split P once, write hi/lo (warp-private rows) ----
#pragma unroll
        for (int ni = 0; ni < 4; ++ni) {
            uint2 h0v, l0v, h1v, l1v;
            split_tf32(sacc[ni][0], h0v.x, l0v.x); split_tf32(sacc[ni][1], h0v.y, l0v.y);
            split_tf32(sacc[ni][2], h1v.x, l1v.x); split_tf32(sacc[ni][3], h1v.y, l1v.y);
            *(uint2*)&sPh[rowA * PST + ni * 8 + 2 * tIG] = h0v;
            *(uint2*)&sPl[rowA * PST + ni * 8 + 2 * tIG] = l0v;
            *(uint2*)&sPh[rowB * PST + ni * 8 + 2 * tIG] = h1v;
            *(uint2*)&sPl[rowB * PST + ni * 8 + 2 * tIG] = l1v;
        }
        __syncwarp();

        // ---- O += P V ----
#pragma unroll
        for (int ks = 0; ks < 4; ++ks) {
            const int pa = rowA * PST + ks * 8 + tIG;
            const int pb = rowB * PST + ks * 8 + tIG;
            unsigned ph[4] = { sPh[pa], sPh[pb], sPh[pa + 4], sPh[pb + 4] };
            unsigned pl[4] = { sPl[pa], sPl[pb], sPl[pa + 4], sPl[pb + 4] };
#pragma unroll
            for (int ni = 0; ni < 8; ++ni) {
                const int vo = (ni * 8 + gID) * PST + ks * 8 + tIG;
                unsigned bh0 = sVh[vo], bh1 = sVh[vo + 4];
                unsigned bl0 = sVl[vo], bl1 = sVl[vo + 4];
                mma_tf32(oacc[ni], ph, bh0, bh1);
                mma_tf32(oacc[ni], ph, bl0, bl1);
                mma_tf32(oacc[ni], pl, bh0, bh1);
            }
        }
    }

    // ---- epilogue: normalize + split, write AO hi/lo ----
    const float i0 = 1.0f / l0, i1 = 1.0f / l1;
    const size_t oa = (size_t)(b * NN + q0 + rowA) * FF + h * HD;
    const size_t ob = (size_t)(b * NN + q0 + rowB) * FF + h * HD;
#pragma unroll
    for (int ni = 0; ni < 8; ++ni) {
        uint2 h0v, l0v, h1v, l1v;
        split_tf32(oacc[ni][0] * i0, h0v.x, l0v.x);
        split_tf32(oacc[ni][1] * i0, h0v.y, l0v.y);
        split_tf32(oacc[ni][2] * i1, h1v.x, l1v.x);
        split_tf32(oacc[ni][3] * i1, h1v.y, l1v.y);
        *(uint2*)&AOh[oa + ni * 8 + 2 * tIG] = h0v;
        *(uint2*)&AOl[oa + ni * 8 + 2 * tIG] = l0v;
        *(uint2*)&AOh[ob + ni * 8 + 2 * tIG] = h1v;
        *(uint2*)&AOl[ob + ni * 8 + 2 * tIG] = l1v;
    }
}

// ============================================================================
// Launch
// ============================================================================
extern "C" void kernel_launch(void* const* d_in, const int* in_sizes, int n_in,
                              void* d_out, int out_size)
{
    (void)in_sizes; (void)n_in; (void)out_size;
    const float* x   = (const float*)d_in[0];
    const float* ef  = (const float*)d_in[1];
    const int*   msk = (const int*)  d_in[2];
    const float* Wq  = (const float*)d_in[3];
    const float* bq  = (const float*)d_in[4];
    const float* Wk  = (const float*)d_in[5];
    const float* bk  = (const float*)d_in[6];
    const float* Wv  = (const float*)d_in[7];
    const float* bv  = (const float*)d_in[8];
    const float* We  = (const float*)d_in[9];
    const float* be  = (const float*)d_in[10];
    const float* Wo  = (const float*)d_in[11];
    const float* bo  = (const float*)d_in[12];
    float* out = (float*)d_out;

    unsigned *pQh, *pQl, *pKh, *pKl, *pVh, *pVl, *pAOh, *pAOl;
    unsigned *pxh, *pxl, *pWqh, *pWql, *pWkh, *pWkl, *pWvh, *pWvl, *pWoh, *pWol;
    float *pBias;
    cudaGetSymbolAddress((void**)&pQh,   g_Qh);
    cudaGetSymbolAddress((void**)&pQl,   g_Ql);
    cudaGetSymbolAddress((void**)&pKh,   g_Kh);
    cudaGetSymbolAddress((void**)&pKl,   g_Kl);
    cudaGetSymbolAddress((void**)&pVh,   g_Vh);
    cudaGetSymbolAddress((void**)&pVl,   g_Vl);
    cudaGetSymbolAddress((void**)&pAOh,  g_AOh);
    cudaGetSymbolAddress((void**)&pAOl,  g_AOl);
    cudaGetSymbolAddress((void**)&pxh,   g_xh);
    cudaGetSymbolAddress((void**)&pxl,   g_xl);
    cudaGetSymbolAddress((void**)&pWqh,  g_Wqh);
    cudaGetSymbolAddress((void**)&pWql,  g_Wql);
    cudaGetSymbolAddress((void**)&pWkh,  g_Wkh);
    cudaGetSymbolAddress((void**)&pWkl,  g_Wkl);
    cudaGetSymbolAddress((void**)&pWvh,  g_Wvh);
    cudaGetSymbolAddress((void**)&pWvl,  g_Wvl);
    cudaGetSymbolAddress((void**)&pWoh,  g_Woh);
    cudaGetSymbolAddress((void**)&pWol,  g_Wol);
    cudaGetSymbolAddress((void**)&pBias, g_bias);

    static int smem_set = 0;
    if (!smem_set) {
        cudaFuncSetAttribute(attn_mma, cudaFuncAttributeMaxDynamicSharedMemorySize,
                             SMEM_ATTN);
        smem_set = 1;
    }

    // ---- one-time splits: x (2M floats) + 4 weight matrices (256K each) ----
    split_kernel<<<(MM * FF / 4) / 256, 256>>>((const float4*)x,  (uint4*)pxh,  (uint4*)pxl);
    split_kernel<<<(FF * FF / 4) / 256, 256>>>((const float4*)Wq, (uint4*)pWqh, (uint4*)pWql);
    split_kernel<<<(FF * FF / 4) / 256, 256>>>((const float4*)Wk, (uint4*)pWkh, (uint4*)pWkl);
    split_kernel<<<(FF * FF / 4) / 256, 256>>>((const float4*)Wv, (uint4*)pWvh, (uint4*)pWvl);
    split_kernel<<<(FF * FF / 4) / 256, 256>>>((const float4*)Wo, (uint4*)pWoh, (uint4*)pWol);

    // ---- QKV fused (mode 0: split outputs; Q pre-scaled by 0.125) ----
    dim3 gqkv(512 / 64, MM / 64, 3);
    gemm_ps<<<gqkv, 128>>>(pxh, pxl,
                           pWqh, pWql, pWkh, pWkl, pWvh, pWvl,
                           bq, bk, bv,
                           nullptr, pQh, pQl, pKh, pKl, pVh, pVl, 0);

    edge_bias_kernel<<<(BB * NN * NN) / 256, 256>>>(
        (const float4*)ef, msk, We, be, pBias);

    attn_mma<<<dim3(NN / 64, HH, BB), 128, SMEM_ATTN>>>(
        pQh, pQl, pKh, pKl, pVh, pVl, pBias, pAOh, pAOl);

    // ---- O-projection (mode 1: float output) ----
    dim3 go(512 / 64, MM / 64, 1);
    gemm_ps<<<go, 128>>>(pAOh, pAOl,
                         pWoh, pWol, pWoh, pWol, pWoh, pWol,
                         bo, bo, bo,
                         out, nullptr, nullptr, nullptr, nullptr, nullptr, nullptr, 1);
}

// round 10
// speedup vs baseline: 1.5260x; 1.5260x over previous
#include <cuda_runtime.h>
#include <cuda_fp16.h>
#include <math.h>

#define BB 4
#define NN 1024
#define FF 512
#define EE 32
#define HH 8
#define HD 64
#define MM (BB*NN)     // 4096
#define WPR 256        // half2 words per 512-float row
#define LOSC 32.0f
#define LOINV 0.03125f

// ---- scratch (static device globals; runtime alloc is forbidden) ----
__device__ unsigned g_xh [MM*WPR], g_xl [MM*WPR];
__device__ unsigned g_Wqh[FF*WPR], g_Wql[FF*WPR];
__device__ unsigned g_Wkh[FF*WPR], g_Wkl[FF*WPR];
__device__ unsigned g_Wvh[FF*WPR], g_Wvl[FF*WPR];
__device__ unsigned g_Woh[FF*WPR], g_Wol[FF*WPR];
__device__ unsigned g_Qh [MM*WPR], g_Ql [MM*WPR];   // lo scaled x32
__device__ unsigned g_Kh [MM*WPR], g_Kl [MM*WPR];   // lo scaled x32
__device__ __half   g_Vth[(size_t)BB*HH*HD*NN];     // V transposed [b][h][d][tok]
__device__ __half   g_Vtl[(size_t)BB*HH*HD*NN];     // lo UNSCALED
__device__ unsigned g_AOh[MM*WPR], g_AOl[MM*WPR];   // lo scaled x32
__device__ float    g_bias[(size_t)BB*HH*NN*NN];

// ============================================================================
// helpers
// ============================================================================
__device__ __forceinline__ unsigned pack_h2(float a, float b) {
    __half2 h = __floats2half2_rn(a, b);
    return *reinterpret_cast<unsigned*>(&h);
}

// 3-term fp16 mma building block: m16n8k16, fp32 accum
__device__ __forceinline__ void mma_f16(float (&d)[4], const unsigned (&a)[4],
                                        unsigned b0, unsigned b1) {
    asm volatile(
        "mma.sync.aligned.m16n8k16.row.col.f32.f16.f16.f32 "
        "{%0,%1,%2,%3}, {%4,%5,%6,%7}, {%8,%9}, {%0,%1,%2,%3};\n"
        : "+f"(d[0]), "+f"(d[1]), "+f"(d[2]), "+f"(d[3])
        : "r"(a[0]), "r"(a[1]), "r"(a[2]), "r"(a[3]), "r"(b0), "r"(b1));
}

__device__ __forceinline__ unsigned long long pk2(float x, float y) {
    unsigned long long r;
    asm("mov.b64 %0, {%1,%2};" : "=l"(r) : "f"(x), "f"(y));
    return r;
}
__device__ __forceinline__ float2 upk2(unsigned long long v) {
    float x, y;
    asm("mov.b64 {%0,%1}, %2;" : "=f"(x), "=f"(y) : "l"(v));
    return make_float2(x, y);
}
__device__ __forceinline__ unsigned long long fma2(unsigned long long a,
                                                   unsigned long long b,
                                                   unsigned long long c) {
    unsigned long long d;
    asm("fma.rn.f32x2 %0, %1, %2, %3;" : "=l"(d) : "l"(a), "l"(b), "l"(c));
    return d;
}

// ============================================================================
// one-time fp16 hi/lo split (lo scaled x32), packed half2 words
// ============================================================================
__global__ __launch_bounds__(256) void split_kernel(
    const float4* __restrict__ src, uint2* __restrict__ H, uint2* __restrict__ L)
{
    const int i = blockIdx.x * 256 + threadIdx.x;
    float4 v = src[i];
    __half hx = __float2half_rn(v.x), hy = __float2half_rn(v.y);
    __half hz = __float2half_rn(v.z), hw = __float2half_rn(v.w);
    float rx = (v.x - __half2float(hx)) * LOSC;
    float ry = (v.y - __half2float(hy)) * LOSC;
    float rz = (v.z - __half2float(hz)) * LOSC;
    float rw = (v.w - __half2float(hw)) * LOSC;
    uint2 h, l;
    h.x = pack_h2(__half2float(hx), __half2float(hy));
    h.y = pack_h2(__half2float(hz), __half2float(hw));
    l.x = pack_h2(rx, ry);
    l.y = pack_h2(rz, rw);
    H[i] = h; L[i] = l;
}

// ============================================================================
// 3-term fp16 GEMM (NT): C[M,512] = A @ W^T + bias.
// BM=128, BN=64, BK=32 (16 words); 256 threads, 8 warps (4m x 2n), warp 32x32.
// Cross terms (x32-scaled lo) in separate accumulator; result = d + dc/32.
// mode 0: z=0 -> Q words (x0.125), z=1 -> K words, z=2 -> V transposed halves.
// mode 1: float C out.
// ============================================================================
#define GST 20
__global__ __launch_bounds__(256, 2) void gemm_f16(
    const unsigned* __restrict__ Ah, const unsigned* __restrict__ Al,
    const unsigned* __restrict__ B0h, const unsigned* __restrict__ B0l,
    const unsigned* __restrict__ B1h, const unsigned* __restrict__ B1l,
    const unsigned* __restrict__ B2h, const unsigned* __restrict__ B2l,
    const float* __restrict__ b0p, const float* __restrict__ b1p,
    const float* __restrict__ b2p,
    float* __restrict__ C,
    unsigned* __restrict__ QH, unsigned* __restrict__ QL,
    unsigned* __restrict__ KH, unsigned* __restrict__ KL,
    __half* __restrict__ VtH, __half* __restrict__ VtL,
    int mode)
{
    const unsigned* Bh  = (blockIdx.z == 0) ? B0h : (blockIdx.z == 1) ? B1h : B2h;
    const unsigned* Bl  = (blockIdx.z == 0) ? B0l : (blockIdx.z == 1) ? B1l : B2l;
    const float*   bias = (blockIdx.z == 0) ? b0p : (blockIdx.z == 1) ? b1p : b2p;

    __shared__ unsigned sAh[128][GST], sAl[128][GST];
    __shared__ unsigned sBh[64][GST],  sBl[64][GST];

    const int tid  = threadIdx.x;
    const int lane = tid & 31;
    const int wid  = tid >> 5;
    const int gID  = lane >> 2;
    const int tIG  = lane & 3;
    const int wm   = (wid >> 1) * 32;
    const int wn   = (wid & 1) * 32;
    const int m0   = blockIdx.y * 128;
    const int n0   = blockIdx.x * 64;

    float d[2][4][4], dc[2][4][4];
#pragma unroll
    for (int mi = 0; mi < 2; ++mi)
#pragma unroll
        for (int ni = 0; ni < 4; ++ni)
#pragma unroll
            for (int r = 0; r < 4; ++r) { d[mi][ni][r] = 0.f; dc[mi][ni][r] = 0.f; }

    for (int k0w = 0; k0w < 256; k0w += 16) {
#pragma unroll
        for (int i = 0; i < 2; ++i) {
            int j = tid + i * 256;
            int row = j >> 2, wc = (j & 3) * 4;
            size_t ga = (size_t)(m0 + row) * WPR + k0w + wc;
            *(uint4*)&sAh[row][wc] = *(const uint4*)(Ah + ga);
            *(uint4*)&sAl[row][wc] = *(const uint4*)(Al + ga);
        }
        {
            int row = tid >> 2, wc = (tid & 3) * 4;
            size_t gb = (size_t)(n0 + row) * WPR + k0w + wc;
            *(uint4*)&sBh[row][wc] = *(const uint4*)(Bh + gb);
            *(uint4*)&sBl[row][wc] = *(const uint4*)(Bl + gb);
        }
        __syncthreads();

#pragma unroll
        for (int ks = 0; ks < 2; ++ks) {
            unsigned bh[4][2], bl[4][2];
#pragma unroll
            for (int ni = 0; ni < 4; ++ni) {
                const int rn = wn + ni * 8 + gID;
                bh[ni][0] = sBh[rn][ks * 8 + tIG];
                bh[ni][1] = sBh[rn][ks * 8 + tIG + 4];
                bl[ni][0] = sBl[rn][ks * 8 + tIG];
                bl[ni][1] = sBl[rn][ks * 8 + tIG + 4];
            }
#pragma unroll
            for (int mi = 0; mi < 2; ++mi) {
                const int ra = wm + mi * 16 + gID;
                unsigned ah[4], al[4];
                ah[0] = sAh[ra    ][ks * 8 + tIG];
                ah[1] = sAh[ra + 8][ks * 8 + tIG];
                ah[2] = sAh[ra    ][ks * 8 + tIG + 4];
                ah[3] = sAh[ra + 8][ks * 8 + tIG + 4];
                al[0] = sAl[ra    ][ks * 8 + tIG];
                al[1] = sAl[ra + 8][ks * 8 + tIG];
                al[2] = sAl[ra    ][ks * 8 + tIG + 4];
                al[3] = sAl[ra + 8][ks * 8 + tIG + 4];
#pragma unroll
                for (int ni = 0; ni < 4; ++ni) {
                    mma_f16(d [mi][ni], ah, bh[ni][0], bh[ni][1]);
                    mma_f16(dc[mi][ni], ah, bl[ni][0], bl[ni][1]);
                    mma_f16(dc[mi][ni], al, bh[ni][0], bh[ni][1]);
                }
            }
        }
        __syncthreads();
    }

    // epilogues
#pragma unroll
    for (int mi = 0; mi < 2; ++mi) {
#pragma unroll
        for (int ni = 0; ni < 4; ++ni) {
            const int row = m0 + wm + mi * 16 + gID;
            const int col = n0 + wn + ni * 8 + 2 * tIG;
            float2 bb = *(const float2*)&bias[col];
            float v00 = fmaf(dc[mi][ni][0], LOINV, d[mi][ni][0]) + bb.x;
            float v01 = fmaf(dc[mi][ni][1], LOINV, d[mi][ni][1]) + bb.y;
            float v10 = fmaf(dc[mi][ni][2], LOINV, d[mi][ni][2]) + bb.x;
            float v11 = fmaf(dc[mi][ni][3], LOINV, d[mi][ni][3]) + bb.y;
            if (mode == 1) {
                *(float2*)&C[(size_t)row * 512 + col]       = make_float2(v00, v01);
                *(float2*)&C[(size_t)(row + 8) * 512 + col] = make_float2(v10, v11);
            } else if (blockIdx.z < 2) {
                unsigned* H = (blockIdx.z == 0) ? QH : KH;
                unsigned* L = (blockIdx.z == 0) ? QL : KL;
                const float sc = (blockIdx.z == 0) ? 0.125f : 1.0f;
                v00 *= sc; v01 *= sc; v10 *= sc; v11 *= sc;
                __half h00 = __float2half_rn(v00), h01 = __float2half_rn(v01);
                __half h10 = __float2half_rn(v10), h11 = __float2half_rn(v11);
                const size_t w0 = (size_t)row * WPR + (col >> 1);
                const size_t w1 = (size_t)(row + 8) * WPR + (col >> 1);
                H[w0] = pack_h2(__half2float(h00), __half2float(h01));
                L[w0] = pack_h2((v00 - __half2float(h00)) * LOSC,
                                (v01 - __half2float(h01)) * LOSC);
                H[w1] = pack_h2(__half2float(h10), __half2float(h11));
                L[w1] = pack_h2((v10 - __half2float(h10)) * LOSC,
                                (v11 - __half2float(h11)) * LOSC);
            } else {
                // V: write transposed [b][h][d][tok], lo UNSCALED
                float vv[4] = { v00, v01, v10, v11 };
#pragma unroll
                for (int u = 0; u < 4; ++u) {
                    const int rr = row + (u >> 1) * 8;
                    const int cc = col + (u & 1);
                    const int bidx = rr >> 10, tok = rr & 1023;
                    const int hh = cc >> 6, dd = cc & 63;
                    const size_t vi = (((size_t)bidx * HH + hh) * HD + dd) * NN + tok;
                    __half hv = __float2half_rn(vv[u]);
                    VtH[vi] = hv;
                    VtL[vi] = __float2half_rn(vv[u] - __half2float(hv));
                }
            }
        }
    }
}

// ============================================================================
// Edge bias (coalesced, smem-staged) — validated R6/R7.
// ============================================================================
__global__ __launch_bounds__(256) void edge_bias_kernel(
    const float4* __restrict__ ef4, const int* __restrict__ mask,
    const float* __restrict__ We, const float* __restrict__ be,
    float* __restrict__ bias)
{
    __shared__ float sE[256 * 33];
    __shared__ unsigned long long sW2[EE][4];
    __shared__ float sbe[HH];

    const int t = threadIdx.x;
    if (t < EE * 4) {
        int e = t >> 2, p = t & 3;
        sW2[e][p] = pk2(We[(2 * p) * EE + e], We[(2 * p + 1) * EE + e]);
    }
    if (t < HH) sbe[t] = be[t];

    const size_t row0 = (size_t)blockIdx.x * 256;
    const size_t base4 = row0 * 8;

#pragma unroll
    for (int i = 0; i < 8; ++i) {
        int j = t + i * 256;
        float4 v = ef4[base4 + j];
        float* dst = &sE[(j >> 3) * 33 + (j & 7) * 4];
        dst[0] = v.x; dst[1] = v.y; dst[2] = v.z; dst[3] = v.w;
    }
    __syncthreads();

    const int mk = mask[row0 + t];

    unsigned long long acc[4];
#pragma unroll
    for (int p = 0; p < 4; ++p) acc[p] = pk2(sbe[2 * p], sbe[2 * p + 1]);

    const float* myrow = &sE[t * 33];
#pragma unroll
    for (int e = 0; e < EE; ++e) {
        float v = myrow[e];
        unsigned long long v2 = pk2(v, v);
#pragma unroll
        for (int p = 0; p < 4; ++p) acc[p] = fma2(v2, sW2[e][p], acc[p]);
    }

    const size_t kq = row0 + t;
    const int k = (int)(kq & (NN - 1));
    const size_t bq = kq >> 10;
    const int q = (int)(bq & (NN - 1));
    const int b = (int)(bq >> 10);

#pragma unroll
    for (int p = 0; p < 4; ++p) {
        float2 o = upk2(acc[p]);
        float o0 = mk ? o.x : -1e30f;
        float o1 = mk ? o.y : -1e30f;
        bias[(((size_t)b * HH + 2 * p    ) * NN + q) * NN + k] = o0;
        bias[(((size_t)b * HH + 2 * p + 1) * NN + q) * NN + k] = o1;
    }
}

// ============================================================================
// Flash attention, 3-term fp16 S (cross-acc), 1-term P x 2-term V for PV.
// CTA = (64 q, head, batch); 4 warps; warp owns 16 q-rows; key-tile 32.
// ============================================================================
#define KTILE 32
#define KSTW 36    // K row stride (words): 32 data + 4 pad
#define VSTW 20    // Vt / P row stride (words): 16 data + 4 pad

__global__ __launch_bounds__(128, 3) void attn_f16(
    const unsigned* __restrict__ QH, const unsigned* __restrict__ QL,
    const unsigned* __restrict__ KH, const unsigned* __restrict__ KL,
    const __half* __restrict__ VtH, const __half* __restrict__ VtL,
    const float* __restrict__ bias,
    unsigned* __restrict__ AOh, unsigned* __restrict__ AOl)
{
    __shared__ unsigned sKh[KTILE][KSTW], sKl[KTILE][KSTW];
    __shared__ unsigned sVh[HD][VSTW],   sVl[HD][VSTW];
    __shared__ unsigned sPh[64][VSTW];

    const int tid  = threadIdx.x;
    const int lane = tid & 31;
    const int wid  = tid >> 5;
    const int gID  = lane >> 2;
    const int tIG  = lane & 3;
    const int wq   = wid * 16;
    const int q0   = blockIdx.x * 64;
    const int h    = blockIdx.y;
    const int b    = blockIdx.z;

    const int rowA = wq + gID;
    const int rowB = wq + gID + 8;

    // ---- Q fragments in regs (hi + scaled lo) ----
    unsigned qh[4][4], ql[4][4];
    {
        const size_t rA = (size_t)(b * NN + q0 + rowA) * WPR + h * 32;
        const size_t rB = (size_t)(b * NN + q0 + rowB) * WPR + h * 32;
#pragma unroll
        for (int ks = 0; ks < 4; ++ks) {
            const int c = ks * 8 + tIG;
            qh[ks][0] = QH[rA + c];     qh[ks][1] = QH[rB + c];
            qh[ks][2] = QH[rA + c + 4]; qh[ks][3] = QH[rB + c + 4];
            ql[ks][0] = QL[rA + c];     ql[ks][1] = QL[rB + c];
            ql[ks][2] = QL[rA + c + 4]; ql[ks][3] = QL[rB + c + 4];
        }
    }

    const float* biasb = bias + ((size_t)b * HH + h) * NN * NN;
    const unsigned* VtHw = (const unsigned*)VtH;
    const unsigned* VtLw = (const unsigned*)VtL;
    const size_t vbase = ((size_t)b * HH + h) * HD * (NN / 2);   // word base

    float m0 = -1e38f, m1 = -1e38f, l0 = 0.f, l1 = 0.f;
    float oacc[8][4];
#pragma unroll
    for (int ni = 0; ni < 8; ++ni)
#pragma unroll
        for (int r = 0; r < 4; ++r) oacc[ni][r] = 0.f;

    for (int kt = 0; kt < NN; kt += KTILE) {
        __syncthreads();
        // ---- load K [key][32 words] and Vt [d][16 words], hi+lo ----
#pragma unroll
        for (int i = 0; i < 2; ++i) {
            int j = tid + i * 128;
            int kr = j >> 3, wc = (j & 7) * 4;
            size_t gk = (size_t)(b * NN + kt + kr) * WPR + h * 32 + wc;
            *(uint4*)&sKh[kr][wc] = *(const uint4*)(KH + gk);
            *(uint4*)&sKl[kr][wc] = *(const uint4*)(KL + gk);
            int dr = j >> 2, vc = (j & 3) * 4;
            size_t gv = vbase + (size_t)dr * (NN / 2) + (kt >> 1) + vc;
            *(uint4*)&sVh[dr][vc] = *(const uint4*)(VtHw + gv);
            *(uint4*)&sVl[dr][vc] = *(const uint4*)(VtLw + gv);
        }
        __syncthreads();

        // ---- S = Q K^T (3-term; cross in separate acc) ----
        float sacc[4][4], scr[4][4];
#pragma unroll
        for (int ni = 0; ni < 4; ++ni)
#pragma unroll
            for (int r = 0; r < 4; ++r) { sacc[ni][r] = 0.f; scr[ni][r] = 0.f; }

#pragma unroll
        for (int ks = 0; ks < 4; ++ks) {
#pragma unroll
            for (int ni = 0; ni < 4; ++ni) {
                const int kr = ni * 8 + gID;
                unsigned kh0 = sKh[kr][ks * 8 + tIG], kh1 = sKh[kr][ks * 8 + tIG + 4];
                unsigned kl0 = sKl[kr][ks * 8 + tIG], kl1 = sKl[kr][ks * 8 + tIG + 4];
                mma_f16(sacc[ni], qh[ks], kh0, kh1);
                mma_f16(scr[ni],  qh[ks], kl0, kl1);
                mma_f16(scr[ni],  ql[ks], kh0, kh1);
            }
        }

        // ---- bias + online softmax ----
        const float* br0 = biasb + (size_t)(q0 + rowA) * NN + kt;
        const float* br1 = biasb + (size_t)(q0 + rowB) * NN + kt;
        float mx0 = -1e38f, mx1 = -1e38f;
#pragma unroll
        for (int ni = 0; ni < 4; ++ni) {
            float2 b0v = *(const float2*)&br0[ni * 8 + 2 * tIG];
            float2 b1v = *(const float2*)&br1[ni * 8 + 2 * tIG];
            sacc[ni][0] = fmaf(scr[ni][0], LOINV, sacc[ni][0]) + b0v.x;
            sacc[ni][1] = fmaf(scr[ni][1], LOINV, sacc[ni][1]) + b0v.y;
            sacc[ni][2] = fmaf(scr[ni][2], LOINV, sacc[ni][2]) + b1v.x;
            sacc[ni][3] = fmaf(scr[ni][3], LOINV, sacc[ni][3]) + b1v.y;
            mx0 = fmaxf(mx0, fmaxf(sacc[ni][0], sacc[ni][1]));
            mx1 = fmaxf(mx1, fmaxf(sacc[ni][2], sacc[ni][3]));
        }
        mx0 = fmaxf(mx0, __shfl_xor_sync(0xffffffffu, mx0, 1));
        mx0 = fmaxf(mx0, __shfl_xor_sync(0xffffffffu, mx0, 2));
        mx1 = fmaxf(mx1, __shfl_xor_sync(0xffffffffu, mx1, 1));
        mx1 = fmaxf(mx1, __shfl_xor_sync(0xffffffffu, mx1, 2));

        const float mn0 = fmaxf(m0, mx0), mn1 = fmaxf(m1, mx1);
        const float c0f = __expf(m0 - mn0), c1f = __expf(m1 - mn1);
        m0 = mn0; m1 = mn1;

        float ps0 = 0.f, ps1 = 0.f;
#pragma unroll
        for (int ni = 0; ni < 4; ++ni) {
            sacc[ni][0] = __expf(sacc[ni][0] - mn0); ps0 += sacc[ni][0];
            sacc[ni][1] = __expf(sacc[ni][1] - mn0); ps0 += sacc[ni][1];
            sacc[ni][2] = __expf(sacc[ni][2] - mn1); ps1 += sacc[ni][2];
            sacc[ni][3] = __expf(sacc[ni][3] - mn1); ps1 += sacc[ni][3];
        }
        ps0 += __shfl_xor_sync(0xffffffffu, ps0, 1);
        ps0 += __shfl_xor_sync(0xffffffffu, ps0, 2);
        ps1 += __shfl_xor_sync(0xffffffffu, ps1, 1);
        ps1 += __shfl_xor_sync(0xffffffffu, ps1, 2);
        l0 = l0 * c0f + ps0;
        l1 = l1 * c1f + ps1;

#pragma unroll
        for (int ni = 0; ni < 8; ++ni) {
            oacc[ni][0] *= c0f; oacc[ni][1] *= c0f;
            oacc[ni][2] *= c1f; oacc[ni][3] *= c1f;
        }

        // ---- P -> fp16 (1-term), warp-private smem rows ----
#pragma unroll
        for (int ni = 0; ni < 4; ++ni) {
            sPh[rowA][ni * 4 + tIG] = pack_h2(sacc[ni][0], sacc[ni][1]);
            sPh[rowB][ni * 4 + tIG] = pack_h2(sacc[ni][2], sacc[ni][3]);
        }
        __syncwarp();

        // ---- O += P V (P 1-term, V 2-term) ----
#pragma unroll
        for (int ks = 0; ks < 2; ++ks) {
            unsigned ph[4];
            ph[0] = sPh[rowA][ks * 8 + tIG];
            ph[1] = sPh[rowB][ks * 8 + tIG];
            ph[2] = sPh[rowA][ks * 8 + tIG + 4];
            ph[3] = sPh[rowB][ks * 8 + tIG + 4];
#pragma unroll
            for (int ni = 0; ni < 8; ++ni) {
                const int dr = ni * 8 + gID;
                unsigned vh0 = sVh[dr][ks * 8 + tIG], vh1 = sVh[dr][ks * 8 + tIG + 4];
                unsigned vl0 = sVl[dr][ks * 8 + tIG], vl1 = sVl[dr][ks * 8 + tIG + 4];
                mma_f16(oacc[ni], ph, vh0, vh1);
                mma_f16(oacc[ni], ph, vl0, vl1);
            }
        }
    }

    // ---- epilogue: normalize + split, write AO hi / lo(x32) words ----
    const float i0 = 1.0f / l0, i1 = 1.0f / l1;
    const size_t oa = (size_t)(b * NN + q0 + rowA) * WPR + h * 32;
    const size_t ob = (size_t)(b * NN + q0 + rowB) * WPR + h * 32;
#pragma unroll
    for (int ni = 0; ni < 8; ++ni) {
        const int w = ni * 4 + tIG;
        float v0 = oacc[ni][0] * i0, v1 = oacc[ni][1] * i0;
        float v2 = oacc[ni][2] * i1, v3 = oacc[ni][3] * i1;
        __half h0 = __float2half_rn(v0), h1 = __float2half_rn(v1);
        __half h2 = __float2half_rn(v2), h3 = __float2half_rn(v3);
        AOh[oa + w] = pack_h2(__half2float(h0), __half2float(h1));
        AOl[oa + w] = pack_h2((v0 - __half2float(h0)) * LOSC,
                              (v1 - __half2float(h1)) * LOSC);
        AOh[ob + w] = pack_h2(__half2float(h2), __half2float(h3));
        AOl[ob + w] = pack_h2((v2 - __half2float(h2)) * LOSC,
                              (v3 - __half2float(h3)) * LOSC);
    }
}

// ============================================================================
// Launch
// ============================================================================
extern "C" void kernel_launch(void* const* d_in, const int* in_sizes, int n_in,
                              void* d_out, int out_size)
{
    (void)in_sizes; (void)n_in; (void)out_size;
    const float* x   = (const float*)d_in[0];
    const float* ef  = (const float*)d_in[1];
    const int*   msk = (const int*)  d_in[2];
    const float* Wq  = (const float*)d_in[3];
    const float* bq  = (const float*)d_in[4];
    const float* Wk  = (const float*)d_in[5];
    const float* bk  = (const float*)d_in[6];
    const float* Wv  = (const float*)d_in[7];
    const float* bv  = (const float*)d_in[8];
    const float* We  = (const float*)d_in[9];
    const float* be  = (const float*)d_in[10];
    const float* Wo  = (const float*)d_in[11];
    const float* bo  = (const float*)d_in[12];
    float* out = (float*)d_out;

    unsigned *pxh, *pxl, *pWqh, *pWql, *pWkh, *pWkl, *pWvh, *pWvl, *pWoh, *pWol;
    unsigned *pQh, *pQl, *pKh, *pKl, *pAOh, *pAOl;
    __half *pVth, *pVtl;
    float *pBias;
    cudaGetSymbolAddress((void**)&pxh,  g_xh);  cudaGetSymbolAddress((void**)&pxl,  g_xl);
    cudaGetSymbolAddress((void**)&pWqh, g_Wqh); cudaGetSymbolAddress((void**)&pWql, g_Wql);
    cudaGetSymbolAddress((void**)&pWkh, g_Wkh); cudaGetSymbolAddress((void**)&pWkl, g_Wkl);
    cudaGetSymbolAddress((void**)&pWvh, g_Wvh); cudaGetSymbolAddress((void**)&pWvl, g_Wvl);
    cudaGetSymbolAddress((void**)&pWoh, g_Woh); cudaGetSymbolAddress((void**)&pWol, g_Wol);
    cudaGetSymbolAddress((void**)&pQh,  g_Qh);  cudaGetSymbolAddress((void**)&pQl,  g_Ql);
    cudaGetSymbolAddress((void**)&pKh,  g_Kh);  cudaGetSymbolAddress((void**)&pKl,  g_Kl);
    cudaGetSymbolAddress((void**)&pVth, g_Vth); cudaGetSymbolAddress((void**)&pVtl, g_Vtl);
    cudaGetSymbolAddress((void**)&pAOh, g_AOh); cudaGetSymbolAddress((void**)&pAOl, g_AOl);
    cudaGetSymbolAddress((void**)&pBias, g_bias);

    // one-time hi/lo splits (lo x32)
    split_kernel<<<(MM * FF / 4) / 256, 256>>>((const float4*)x,  (uint2*)pxh,  (uint2*)pxl);
    split_kernel<<<(FF * FF / 4) / 256, 256>>>((const float4*)Wq, (uint2*)pWqh, (uint2*)pWql);
    split_kernel<<<(FF * FF / 4) / 256, 256>>>((const float4*)Wk, (uint2*)pWkh, (uint2*)pWkl);
    split_kernel<<<(FF * FF / 4) / 256, 256>>>((const float4*)Wv, (uint2*)pWvh, (uint2*)pWvl);
    split_kernel<<<(FF * FF / 4) / 256, 256>>>((const float4*)Wo, (uint2*)pWoh, (uint2*)pWol);

    // QKV fused (mode 0): Q/K word arrays + V transposed halves
    dim3 gqkv(512 / 64, MM / 128, 3);
    gemm_f16<<<gqkv, 256>>>(pxh, pxl,
                            pWqh, pWql, pWkh, pWkl, pWvh, pWvl,
                            bq, bk, bv,
                            nullptr, pQh, pQl, pKh, pKl, pVth, pVtl, 0);

    edge_bias_kernel<<<(BB * NN * NN) / 256, 256>>>(
        (const float4*)ef, msk, We, be, pBias);

    attn_f16<<<dim3(NN / 64, HH, BB), 128>>>(
        pQh, pQl, pKh, pKl, pVth, pVtl, pBias, pAOh, pAOl);

    // O-projection (mode 1): float out
    dim3 go(512 / 64, MM / 128, 1);
    gemm_f16<<<go, 256>>>(pAOh, pAOl,
                          pWoh, pWol, pWoh, pWol, pWoh, pWol,
                          bo, bo, bo,
                          out, nullptr, nullptr, nullptr, nullptr,
                          nullptr, nullptr, 1);
}

// round 11
// speedup vs baseline: 1.5703x; 1.0290x over previous
#include <cuda_runtime.h>
#include <cuda_fp16.h>
#include <math.h>

#define BB 4
#define NN 1024
#define FF 512
#define EE 32
#define HH 8
#define HD 64
#define MM (BB*NN)     // 4096
#define WPR 256        // half2 words per 512-float row
#define LOSC 32.0f
#define LOINV 0.03125f

// ---- scratch (static device globals; runtime alloc is forbidden) ----
__device__ unsigned g_xh [MM*WPR], g_xl [MM*WPR];
__device__ unsigned g_Wqh[FF*WPR], g_Wql[FF*WPR];
__device__ unsigned g_Wkh[FF*WPR], g_Wkl[FF*WPR];
__device__ unsigned g_Wvh[FF*WPR], g_Wvl[FF*WPR];
__device__ unsigned g_Woh[FF*WPR], g_Wol[FF*WPR];
__device__ unsigned g_Qh [MM*WPR], g_Ql [MM*WPR];   // lo scaled x32
__device__ unsigned g_Kh [MM*WPR], g_Kl [MM*WPR];   // lo scaled x32
__device__ __half   g_Vth[(size_t)BB*HH*HD*NN];     // V transposed [b][h][d][tok]
__device__ __half   g_Vtl[(size_t)BB*HH*HD*NN];     // lo UNSCALED
__device__ unsigned g_AOh[MM*WPR], g_AOl[MM*WPR];   // lo scaled x32
__device__ float    g_bias[(size_t)BB*HH*NN*NN];

// ============================================================================
// helpers
// ============================================================================
__device__ __forceinline__ unsigned pack_h2(float a, float b) {
    __half2 h = __floats2half2_rn(a, b);
    return *reinterpret_cast<unsigned*>(&h);
}

__device__ __forceinline__ void mma_f16(float (&d)[4], const unsigned (&a)[4],
                                        unsigned b0, unsigned b1) {
    asm volatile(
        "mma.sync.aligned.m16n8k16.row.col.f32.f16.f16.f32 "
        "{%0,%1,%2,%3}, {%4,%5,%6,%7}, {%8,%9}, {%0,%1,%2,%3};\n"
        : "+f"(d[0]), "+f"(d[1]), "+f"(d[2]), "+f"(d[3])
        : "r"(a[0]), "r"(a[1]), "r"(a[2]), "r"(a[3]), "r"(b0), "r"(b1));
}

__device__ __forceinline__ unsigned long long pk2(float x, float y) {
    unsigned long long r;
    asm("mov.b64 %0, {%1,%2};" : "=l"(r) : "f"(x), "f"(y));
    return r;
}
__device__ __forceinline__ float2 upk2(unsigned long long v) {
    float x, y;
    asm("mov.b64 {%0,%1}, %2;" : "=f"(x), "=f"(y) : "l"(v));
    return make_float2(x, y);
}
__device__ __forceinline__ unsigned long long fma2(unsigned long long a,
                                                   unsigned long long b,
                                                   unsigned long long c) {
    unsigned long long d;
    asm("fma.rn.f32x2 %0, %1, %2, %3;" : "=l"(d) : "l"(a), "l"(b), "l"(c));
    return d;
}

// ============================================================================
// one-time fp16 hi/lo split (lo scaled x32), packed half2 words
// ============================================================================
__global__ __launch_bounds__(256) void split_kernel(
    const float4* __restrict__ src, uint2* __restrict__ H, uint2* __restrict__ L)
{
    const int i = blockIdx.x * 256 + threadIdx.x;
    float4 v = src[i];
    __half hx = __float2half_rn(v.x), hy = __float2half_rn(v.y);
    __half hz = __float2half_rn(v.z), hw = __float2half_rn(v.w);
    float rx = (v.x - __half2float(hx)) * LOSC;
    float ry = (v.y - __half2float(hy)) * LOSC;
    float rz = (v.z - __half2float(hz)) * LOSC;
    float rw = (v.w - __half2float(hw)) * LOSC;
    uint2 h, l;
    h.x = pack_h2(__half2float(hx), __half2float(hy));
    h.y = pack_h2(__half2float(hz), __half2float(hw));
    l.x = pack_h2(rx, ry);
    l.y = pack_h2(rz, rw);
    H[i] = h; L[i] = l;
}

// ============================================================================
// 3-term fp16 GEMM (NT) — validated R10. BM=128, BN=64, BK=32 (16 words).
// ============================================================================
#define GST 20
__global__ __launch_bounds__(256, 2) void gemm_f16(
    const unsigned* __restrict__ Ah, const unsigned* __restrict__ Al,
    const unsigned* __restrict__ B0h, const unsigned* __restrict__ B0l,
    const unsigned* __restrict__ B1h, const unsigned* __restrict__ B1l,
    const unsigned* __restrict__ B2h, const unsigned* __restrict__ B2l,
    const float* __restrict__ b0p, const float* __restrict__ b1p,
    const float* __restrict__ b2p,
    float* __restrict__ C,
    unsigned* __restrict__ QH, unsigned* __restrict__ QL,
    unsigned* __restrict__ KH, unsigned* __restrict__ KL,
    __half* __restrict__ VtH, __half* __restrict__ VtL,
    int mode)
{
    const unsigned* Bh  = (blockIdx.z == 0) ? B0h : (blockIdx.z == 1) ? B1h : B2h;
    const unsigned* Bl  = (blockIdx.z == 0) ? B0l : (blockIdx.z == 1) ? B1l : B2l;
    const float*   bias = (blockIdx.z == 0) ? b0p : (blockIdx.z == 1) ? b1p : b2p;

    __shared__ unsigned sAh[128][GST], sAl[128][GST];
    __shared__ unsigned sBh[64][GST],  sBl[64][GST];

    const int tid  = threadIdx.x;
    const int lane = tid & 31;
    const int wid  = tid >> 5;
    const int gID  = lane >> 2;
    const int tIG  = lane & 3;
    const int wm   = (wid >> 1) * 32;
    const int wn   = (wid & 1) * 32;
    const int m0   = blockIdx.y * 128;
    const int n0   = blockIdx.x * 64;

    float d[2][4][4], dc[2][4][4];
#pragma unroll
    for (int mi = 0; mi < 2; ++mi)
#pragma unroll
        for (int ni = 0; ni < 4; ++ni)
#pragma unroll
            for (int r = 0; r < 4; ++r) { d[mi][ni][r] = 0.f; dc[mi][ni][r] = 0.f; }

    for (int k0w = 0; k0w < 256; k0w += 16) {
#pragma unroll
        for (int i = 0; i < 2; ++i) {
            int j = tid + i * 256;
            int row = j >> 2, wc = (j & 3) * 4;
            size_t ga = (size_t)(m0 + row) * WPR + k0w + wc;
            *(uint4*)&sAh[row][wc] = *(const uint4*)(Ah + ga);
            *(uint4*)&sAl[row][wc] = *(const uint4*)(Al + ga);
        }
        {
            int row = tid >> 2, wc = (tid & 3) * 4;
            size_t gb = (size_t)(n0 + row) * WPR + k0w + wc;
            *(uint4*)&sBh[row][wc] = *(const uint4*)(Bh + gb);
            *(uint4*)&sBl[row][wc] = *(const uint4*)(Bl + gb);
        }
        __syncthreads();

#pragma unroll
        for (int ks = 0; ks < 2; ++ks) {
            unsigned bh[4][2], bl[4][2];
#pragma unroll
            for (int ni = 0; ni < 4; ++ni) {
                const int rn = wn + ni * 8 + gID;
                bh[ni][0] = sBh[rn][ks * 8 + tIG];
                bh[ni][1] = sBh[rn][ks * 8 + tIG + 4];
                bl[ni][0] = sBl[rn][ks * 8 + tIG];
                bl[ni][1] = sBl[rn][ks * 8 + tIG + 4];
            }
#pragma unroll
            for (int mi = 0; mi < 2; ++mi) {
                const int ra = wm + mi * 16 + gID;
                unsigned ah[4], al[4];
                ah[0] = sAh[ra    ][ks * 8 + tIG];
                ah[1] = sAh[ra + 8][ks * 8 + tIG];
                ah[2] = sAh[ra    ][ks * 8 + tIG + 4];
                ah[3] = sAh[ra + 8][ks * 8 + tIG + 4];
                al[0] = sAl[ra    ][ks * 8 + tIG];
                al[1] = sAl[ra + 8][ks * 8 + tIG];
                al[2] = sAl[ra    ][ks * 8 + tIG + 4];
                al[3] = sAl[ra + 8][ks * 8 + tIG + 4];
#pragma unroll
                for (int ni = 0; ni < 4; ++ni) {
                    mma_f16(d [mi][ni], ah, bh[ni][0], bh[ni][1]);
                    mma_f16(dc[mi][ni], ah, bl[ni][0], bl[ni][1]);
                    mma_f16(dc[mi][ni], al, bh[ni][0], bh[ni][1]);
                }
            }
        }
        __syncthreads();
    }

#pragma unroll
    for (int mi = 0; mi < 2; ++mi) {
#pragma unroll
        for (int ni = 0; ni < 4; ++ni) {
            const int row = m0 + wm + mi * 16 + gID;
            const int col = n0 + wn + ni * 8 + 2 * tIG;
            float2 bb = *(const float2*)&bias[col];
            float v00 = fmaf(dc[mi][ni][0], LOINV, d[mi][ni][0]) + bb.x;
            float v01 = fmaf(dc[mi][ni][1], LOINV, d[mi][ni][1]) + bb.y;
            float v10 = fmaf(dc[mi][ni][2], LOINV, d[mi][ni][2]) + bb.x;
            float v11 = fmaf(dc[mi][ni][3], LOINV, d[mi][ni][3]) + bb.y;
            if (mode == 1) {
                *(float2*)&C[(size_t)row * 512 + col]       = make_float2(v00, v01);
                *(float2*)&C[(size_t)(row + 8) * 512 + col] = make_float2(v10, v11);
            } else if (blockIdx.z < 2) {
                unsigned* H = (blockIdx.z == 0) ? QH : KH;
                unsigned* L = (blockIdx.z == 0) ? QL : KL;
                const float sc = (blockIdx.z == 0) ? 0.125f : 1.0f;
                v00 *= sc; v01 *= sc; v10 *= sc; v11 *= sc;
                __half h00 = __float2half_rn(v00), h01 = __float2half_rn(v01);
                __half h10 = __float2half_rn(v10), h11 = __float2half_rn(v11);
                const size_t w0 = (size_t)row * WPR + (col >> 1);
                const size_t w1 = (size_t)(row + 8) * WPR + (col >> 1);
                H[w0] = pack_h2(__half2float(h00), __half2float(h01));
                L[w0] = pack_h2((v00 - __half2float(h00)) * LOSC,
                                (v01 - __half2float(h01)) * LOSC);
                H[w1] = pack_h2(__half2float(h10), __half2float(h11));
                L[w1] = pack_h2((v10 - __half2float(h10)) * LOSC,
                                (v11 - __half2float(h11)) * LOSC);
            } else {
                float vv[4] = { v00, v01, v10, v11 };
#pragma unroll
                for (int u = 0; u < 4; ++u) {
                    const int rr = row + (u >> 1) * 8;
                    const int cc = col + (u & 1);
                    const int bidx = rr >> 10, tok = rr & 1023;
                    const int hh = cc >> 6, dd = cc & 63;
                    const size_t vi = (((size_t)bidx * HH + hh) * HD + dd) * NN + tok;
                    __half hv = __float2half_rn(vv[u]);
                    VtH[vi] = hv;
                    VtL[vi] = __float2half_rn(vv[u] - __half2float(hv));
                }
            }
        }
    }
}

// ============================================================================
// Edge bias (coalesced, smem-staged) — validated R6-R10. Runs on side stream.
// ============================================================================
__global__ __launch_bounds__(256) void edge_bias_kernel(
    const float4* __restrict__ ef4, const int* __restrict__ mask,
    const float* __restrict__ We, const float* __restrict__ be,
    float* __restrict__ bias)
{
    __shared__ float sE[256 * 33];
    __shared__ unsigned long long sW2[EE][4];
    __shared__ float sbe[HH];

    const int t = threadIdx.x;
    if (t < EE * 4) {
        int e = t >> 2, p = t & 3;
        sW2[e][p] = pk2(We[(2 * p) * EE + e], We[(2 * p + 1) * EE + e]);
    }
    if (t < HH) sbe[t] = be[t];

    const size_t row0 = (size_t)blockIdx.x * 256;
    const size_t base4 = row0 * 8;

#pragma unroll
    for (int i = 0; i < 8; ++i) {
        int j = t + i * 256;
        float4 v = ef4[base4 + j];
        float* dst = &sE[(j >> 3) * 33 + (j & 7) * 4];
        dst[0] = v.x; dst[1] = v.y; dst[2] = v.z; dst[3] = v.w;
    }
    __syncthreads();

    const int mk = mask[row0 + t];

    unsigned long long acc[4];
#pragma unroll
    for (int p = 0; p < 4; ++p) acc[p] = pk2(sbe[2 * p], sbe[2 * p + 1]);

    const float* myrow = &sE[t * 33];
#pragma unroll
    for (int e = 0; e < EE; ++e) {
        float v = myrow[e];
        unsigned long long v2 = pk2(v, v);
#pragma unroll
        for (int p = 0; p < 4; ++p) acc[p] = fma2(v2, sW2[e][p], acc[p]);
    }

    const size_t kq = row0 + t;
    const int k = (int)(kq & (NN - 1));
    const size_t bq = kq >> 10;
    const int q = (int)(bq & (NN - 1));
    const int b = (int)(bq >> 10);

#pragma unroll
    for (int p = 0; p < 4; ++p) {
        float2 o = upk2(acc[p]);
        float o0 = mk ? o.x : -1e30f;
        float o1 = mk ? o.y : -1e30f;
        bias[(((size_t)b * HH + 2 * p    ) * NN + q) * NN + k] = o0;
        bias[(((size_t)b * HH + 2 * p + 1) * NN + q) * NN + k] = o1;
    }
}

// ============================================================================
// Flash attention (R10 math) + smem-staged bias tile (coalesced LDG).
// ============================================================================
#define KTILE 32
#define KSTW 36
#define VSTW 20
#define BSTW 36    // bias tile stride (floats)

__global__ __launch_bounds__(128, 3) void attn_f16(
    const unsigned* __restrict__ QH, const unsigned* __restrict__ QL,
    const unsigned* __restrict__ KH, const unsigned* __restrict__ KL,
    const __half* __restrict__ VtH, const __half* __restrict__ VtL,
    const float* __restrict__ bias,
    unsigned* __restrict__ AOh, unsigned* __restrict__ AOl)
{
    __shared__ unsigned sKh[KTILE][KSTW], sKl[KTILE][KSTW];
    __shared__ unsigned sVh[HD][VSTW],   sVl[HD][VSTW];
    __shared__ unsigned sPh[64][VSTW];
    __shared__ float    sB[64][BSTW];

    const int tid  = threadIdx.x;
    const int lane = tid & 31;
    const int wid  = tid >> 5;
    const int gID  = lane >> 2;
    const int tIG  = lane & 3;
    const int wq   = wid * 16;
    const int q0   = blockIdx.x * 64;
    const int h    = blockIdx.y;
    const int b    = blockIdx.z;

    const int rowA = wq + gID;
    const int rowB = wq + gID + 8;

    // ---- Q fragments in regs (hi + scaled lo) ----
    unsigned qh[4][4], ql[4][4];
    {
        const size_t rA = (size_t)(b * NN + q0 + rowA) * WPR + h * 32;
        const size_t rB = (size_t)(b * NN + q0 + rowB) * WPR + h * 32;
#pragma unroll
        for (int ks = 0; ks < 4; ++ks) {
            const int c = ks * 8 + tIG;
            qh[ks][0] = QH[rA + c];     qh[ks][1] = QH[rB + c];
            qh[ks][2] = QH[rA + c + 4]; qh[ks][3] = QH[rB + c + 4];
            ql[ks][0] = QL[rA + c];     ql[ks][1] = QL[rB + c];
            ql[ks][2] = QL[rA + c + 4]; ql[ks][3] = QL[rB + c + 4];
        }
    }

    const float* biasb = bias + ((size_t)b * HH + h) * NN * NN;
    const unsigned* VtHw = (const unsigned*)VtH;
    const unsigned* VtLw = (const unsigned*)VtL;
    const size_t vbase = ((size_t)b * HH + h) * HD * (NN / 2);

    float m0 = -1e38f, m1 = -1e38f, l0 = 0.f, l1 = 0.f;
    float oacc[8][4];
#pragma unroll
    for (int ni = 0; ni < 8; ++ni)
#pragma unroll
        for (int r = 0; r < 4; ++r) oacc[ni][r] = 0.f;

    for (int kt = 0; kt < NN; kt += KTILE) {
        __syncthreads();
        // ---- load K, Vt (hi+lo) and the 64x32 bias tile (all coalesced) ----
#pragma unroll
        for (int i = 0; i < 2; ++i) {
            int j = tid + i * 128;
            int kr = j >> 3, wc = (j & 7) * 4;
            size_t gk = (size_t)(b * NN + kt + kr) * WPR + h * 32 + wc;
            *(uint4*)&sKh[kr][wc] = *(const uint4*)(KH + gk);
            *(uint4*)&sKl[kr][wc] = *(const uint4*)(KL + gk);
            int dr = j >> 2, vc = (j & 3) * 4;
            size_t gv = vbase + (size_t)dr * (NN / 2) + (kt >> 1) + vc;
            *(uint4*)&sVh[dr][vc] = *(const uint4*)(VtHw + gv);
            *(uint4*)&sVl[dr][vc] = *(const uint4*)(VtLw + gv);
        }
#pragma unroll
        for (int i = 0; i < 4; ++i) {
            int j = tid + i * 128;
            int brow = j >> 3, bc = (j & 7) * 4;
            *(float4*)&sB[brow][bc] =
                *(const float4*)(biasb + (size_t)(q0 + brow) * NN + kt + bc);
        }
        __syncthreads();

        // ---- S = Q K^T (3-term; cross in separate acc) ----
        float sacc[4][4], scr[4][4];
#pragma unroll
        for (int ni = 0; ni < 4; ++ni)
#pragma unroll
            for (int r = 0; r < 4; ++r) { sacc[ni][r] = 0.f; scr[ni][r] = 0.f; }

#pragma unroll
        for (int ks = 0; ks < 4; ++ks) {
#pragma unroll
            for (int ni = 0; ni < 4; ++ni) {
                const int kr = ni * 8 + gID;
                unsigned kh0 = sKh[kr][ks * 8 + tIG], kh1 = sKh[kr][ks * 8 + tIG + 4];
                unsigned kl0 = sKl[kr][ks * 8 + tIG], kl1 = sKl[kr][ks * 8 + tIG + 4];
                mma_f16(sacc[ni], qh[ks], kh0, kh1);
                mma_f16(scr[ni],  qh[ks], kl0, kl1);
                mma_f16(scr[ni],  ql[ks], kh0, kh1);
            }
        }

        // ---- bias (from smem) + online softmax ----
        float mx0 = -1e38f, mx1 = -1e38f;
#pragma unroll
        for (int ni = 0; ni < 4; ++ni) {
            float2 b0v = *(const float2*)&sB[rowA][ni * 8 + 2 * tIG];
            float2 b1v = *(const float2*)&sB[rowB][ni * 8 + 2 * tIG];
            sacc[ni][0] = fmaf(scr[ni][0], LOINV, sacc[ni][0]) + b0v.x;
            sacc[ni][1] = fmaf(scr[ni][1], LOINV, sacc[ni][1]) + b0v.y;
            sacc[ni][2] = fmaf(scr[ni][2], LOINV, sacc[ni][2]) + b1v.x;
            sacc[ni][3] = fmaf(scr[ni][3], LOINV, sacc[ni][3]) + b1v.y;
            mx0 = fmaxf(mx0, fmaxf(sacc[ni][0], sacc[ni][1]));
            mx1 = fmaxf(mx1, fmaxf(sacc[ni][2], sacc[ni][3]));
        }
        mx0 = fmaxf(mx0, __shfl_xor_sync(0xffffffffu, mx0, 1));
        mx0 = fmaxf(mx0, __shfl_xor_sync(0xffffffffu, mx0, 2));
        mx1 = fmaxf(mx1, __shfl_xor_sync(0xffffffffu, mx1, 1));
        mx1 = fmaxf(mx1, __shfl_xor_sync(0xffffffffu, mx1, 2));

        const float mn0 = fmaxf(m0, mx0), mn1 = fmaxf(m1, mx1);
        const float c0f = __expf(m0 - mn0), c1f = __expf(m1 - mn1);
        m0 = mn0; m1 = mn1;

        float ps0 = 0.f, ps1 = 0.f;
#pragma unroll
        for (int ni = 0; ni < 4; ++ni) {
            sacc[ni][0] = __expf(sacc[ni][0] - mn0); ps0 += sacc[ni][0];
            sacc[ni][1] = __expf(sacc[ni][1] - mn0); ps0 += sacc[ni][1];
            sacc[ni][2] = __expf(sacc[ni][2] - mn1); ps1 += sacc[ni][2];
            sacc[ni][3] = __expf(sacc[ni][3] - mn1); ps1 += sacc[ni][3];
        }
        ps0 += __shfl_xor_sync(0xffffffffu, ps0, 1);
        ps0 += __shfl_xor_sync(0xffffffffu, ps0, 2);
        ps1 += __shfl_xor_sync(0xffffffffu, ps1, 1);
        ps1 += __shfl_xor_sync(0xffffffffu, ps1, 2);
        l0 = l0 * c0f + ps0;
        l1 = l1 * c1f + ps1;

#pragma unroll
        for (int ni = 0; ni < 8; ++ni) {
            oacc[ni][0] *= c0f; oacc[ni][1] *= c0f;
            oacc[ni][2] *= c1f; oacc[ni][3] *= c1f;
        }

        // ---- P -> fp16 (1-term), warp-private smem rows ----
#pragma unroll
        for (int ni = 0; ni < 4; ++ni) {
            sPh[rowA][ni * 4 + tIG] = pack_h2(sacc[ni][0], sacc[ni][1]);
            sPh[rowB][ni * 4 + tIG] = pack_h2(sacc[ni][2], sacc[ni][3]);
        }
        __syncwarp();

        // ---- O += P V (P 1-term, V 2-term) ----
#pragma unroll
        for (int ks = 0; ks < 2; ++ks) {
            unsigned ph[4];
            ph[0] = sPh[rowA][ks * 8 + tIG];
            ph[1] = sPh[rowB][ks * 8 + tIG];
            ph[2] = sPh[rowA][ks * 8 + tIG + 4];
            ph[3] = sPh[rowB][ks * 8 + tIG + 4];
#pragma unroll
            for (int ni = 0; ni < 8; ++ni) {
                const int dr = ni * 8 + gID;
                unsigned vh0 = sVh[dr][ks * 8 + tIG], vh1 = sVh[dr][ks * 8 + tIG + 4];
                unsigned vl0 = sVl[dr][ks * 8 + tIG], vl1 = sVl[dr][ks * 8 + tIG + 4];
                mma_f16(oacc[ni], ph, vh0, vh1);
                mma_f16(oacc[ni], ph, vl0, vl1);
            }
        }
    }

    // ---- epilogue: normalize + split, write AO hi / lo(x32) words ----
    const float i0 = 1.0f / l0, i1 = 1.0f / l1;
    const size_t oa = (size_t)(b * NN + q0 + rowA) * WPR + h * 32;
    const size_t ob = (size_t)(b * NN + q0 + rowB) * WPR + h * 32;
#pragma unroll
    for (int ni = 0; ni < 8; ++ni) {
        const int w = ni * 4 + tIG;
        float v0 = oacc[ni][0] * i0, v1 = oacc[ni][1] * i0;
        float v2 = oacc[ni][2] * i1, v3 = oacc[ni][3] * i1;
        __half h0 = __float2half_rn(v0), h1 = __float2half_rn(v1);
        __half h2 = __float2half_rn(v2), h3 = __float2half_rn(v3);
        AOh[oa + w] = pack_h2(__half2float(h0), __half2float(h1));
        AOl[oa + w] = pack_h2((v0 - __half2float(h0)) * LOSC,
                              (v1 - __half2float(h1)) * LOSC);
        AOh[ob + w] = pack_h2(__half2float(h2), __half2float(h3));
        AOl[ob + w] = pack_h2((v2 - __half2float(h2)) * LOSC,
                              (v3 - __half2float(h3)) * LOSC);
    }
}

// ============================================================================
// Launch — edge bias forked onto a side stream (overlaps splits + QKV GEMM).
// ============================================================================
extern "C" void kernel_launch(void* const* d_in, const int* in_sizes, int n_in,
                              void* d_out, int out_size)
{
    (void)in_sizes; (void)n_in; (void)out_size;
    const float* x   = (const float*)d_in[0];
    const float* ef  = (const float*)d_in[1];
    const int*   msk = (const int*)  d_in[2];
    const float* Wq  = (const float*)d_in[3];
    const float* bq  = (const float*)d_in[4];
    const float* Wk  = (const float*)d_in[5];
    const float* bk  = (const float*)d_in[6];
    const float* Wv  = (const float*)d_in[7];
    const float* bv  = (const float*)d_in[8];
    const float* We  = (const float*)d_in[9];
    const float* be  = (const float*)d_in[10];
    const float* Wo  = (const float*)d_in[11];
    const float* bo  = (const float*)d_in[12];
    float* out = (float*)d_out;

    unsigned *pxh, *pxl, *pWqh, *pWql, *pWkh, *pWkl, *pWvh, *pWvl, *pWoh, *pWol;
    unsigned *pQh, *pQl, *pKh, *pKl, *pAOh, *pAOl;
    __half *pVth, *pVtl;
    float *pBias;
    cudaGetSymbolAddress((void**)&pxh,  g_xh);  cudaGetSymbolAddress((void**)&pxl,  g_xl);
    cudaGetSymbolAddress((void**)&pWqh, g_Wqh); cudaGetSymbolAddress((void**)&pWql, g_Wql);
    cudaGetSymbolAddress((void**)&pWkh, g_Wkh); cudaGetSymbolAddress((void**)&pWkl, g_Wkl);
    cudaGetSymbolAddress((void**)&pWvh, g_Wvh); cudaGetSymbolAddress((void**)&pWvl, g_Wvl);
    cudaGetSymbolAddress((void**)&pWoh, g_Woh); cudaGetSymbolAddress((void**)&pWol, g_Wol);
    cudaGetSymbolAddress((void**)&pQh,  g_Qh);  cudaGetSymbolAddress((void**)&pQl,  g_Ql);
    cudaGetSymbolAddress((void**)&pKh,  g_Kh);  cudaGetSymbolAddress((void**)&pKl,  g_Kl);
    cudaGetSymbolAddress((void**)&pVth, g_Vth); cudaGetSymbolAddress((void**)&pVtl, g_Vtl);
    cudaGetSymbolAddress((void**)&pAOh, g_AOh); cudaGetSymbolAddress((void**)&pAOl, g_AOl);
    cudaGetSymbolAddress((void**)&pBias, g_bias);

    // one-time resources (created on the uncaptured correctness call)
    static cudaStream_t s_edge = nullptr;
    static cudaEvent_t ev_fork = nullptr, ev_join = nullptr;
    if (!s_edge) {
        cudaStreamCreateWithFlags(&s_edge, cudaStreamNonBlocking);
        cudaEventCreateWithFlags(&ev_fork, cudaEventDisableTiming);
        cudaEventCreateWithFlags(&ev_join, cudaEventDisableTiming);
    }

    // ---- fork: edge bias (pure DRAM) runs concurrently with splits + QKV ----
    cudaEventRecord(ev_fork, 0);
    cudaStreamWaitEvent(s_edge, ev_fork, 0);
    edge_bias_kernel<<<(BB * NN * NN) / 256, 256, 0, s_edge>>>(
        (const float4*)ef, msk, We, be, pBias);
    cudaEventRecord(ev_join, s_edge);

    // ---- main chain: splits -> QKV ----
    split_kernel<<<(MM * FF / 4) / 256, 256>>>((const float4*)x,  (uint2*)pxh,  (uint2*)pxl);
    split_kernel<<<(FF * FF / 4) / 256, 256>>>((const float4*)Wq, (uint2*)pWqh, (uint2*)pWql);
    split_kernel<<<(FF * FF / 4) / 256, 256>>>((const float4*)Wk, (uint2*)pWkh, (uint2*)pWkl);
    split_kernel<<<(FF * FF / 4) / 256, 256>>>((const float4*)Wv, (uint2*)pWvh, (uint2*)pWvl);
    split_kernel<<<(FF * FF / 4) / 256, 256>>>((const float4*)Wo, (uint2*)pWoh, (uint2*)pWol);

    dim3 gqkv(512 / 64, MM / 128, 3);
    gemm_f16<<<gqkv, 256>>>(pxh, pxl,
                            pWqh, pWql, pWkh, pWkl, pWvh, pWvl,
                            bq, bk, bv,
                            nullptr, pQh, pQl, pKh, pKl, pVth, pVtl, 0);

    // ---- join: attn needs both QKV and bias ----
    cudaStreamWaitEvent(0, ev_join, 0);

    attn_f16<<<dim3(NN / 64, HH, BB), 128>>>(
        pQh, pQl, pKh, pKl, pVth, pVtl, pBias, pAOh, pAOl);

    dim3 go(512 / 64, MM / 128, 1);
    gemm_f16<<<go, 256>>>(pAOh, pAOl,
                          pWoh, pWol, pWoh, pWol, pWoh, pWol,
                          bo, bo, bo,
                          out, nullptr, nullptr, nullptr, nullptr,
                          nullptr, nullptr, 1);
}

// round 12
// speedup vs baseline: 1.8298x; 1.1652x over previous
#include <cuda_runtime.h>
#include <cuda_fp16.h>
#include <math.h>

#define BB 4
#define NN 1024
#define FF 512
#define EE 32
#define HH 8
#define HD 64
#define MM (BB*NN)     // 4096
#define WPR 256        // half2 words per 512-float row
#define LOSC 32.0f
#define LOINV 0.03125f

// ---- scratch (static device globals; runtime alloc is forbidden) ----
__device__ unsigned g_xh [MM*WPR], g_xl [MM*WPR];
__device__ unsigned g_Wqh[FF*WPR], g_Wql[FF*WPR];
__device__ unsigned g_Wkh[FF*WPR], g_Wkl[FF*WPR];
__device__ unsigned g_Wvh[FF*WPR], g_Wvl[FF*WPR];
__device__ unsigned g_Woh[FF*WPR], g_Wol[FF*WPR];
__device__ unsigned g_Qh [MM*WPR], g_Ql [MM*WPR];   // lo scaled x32
__device__ unsigned g_Kh [MM*WPR], g_Kl [MM*WPR];   // lo scaled x32
__device__ __half   g_Vth[(size_t)BB*HH*HD*NN];     // V transposed [b][h][d][tok]
__device__ __half   g_Vtl[(size_t)BB*HH*HD*NN];     // lo UNSCALED
__device__ unsigned g_AOh[MM*WPR], g_AOl[MM*WPR];   // lo scaled x32
__device__ float    g_bias[(size_t)BB*HH*NN*NN];

// ============================================================================
// helpers
// ============================================================================
__device__ __forceinline__ unsigned pack_h2(float a, float b) {
    __half2 h = __floats2half2_rn(a, b);
    return *reinterpret_cast<unsigned*>(&h);
}

__device__ __forceinline__ void mma_f16(float (&d)[4], const unsigned (&a)[4],
                                        unsigned b0, unsigned b1) {
    asm volatile(
        "mma.sync.aligned.m16n8k16.row.col.f32.f16.f16.f32 "
        "{%0,%1,%2,%3}, {%4,%5,%6,%7}, {%8,%9}, {%0,%1,%2,%3};\n"
        : "+f"(d[0]), "+f"(d[1]), "+f"(d[2]), "+f"(d[3])
        : "r"(a[0]), "r"(a[1]), "r"(a[2]), "r"(a[3]), "r"(b0), "r"(b1));
}

__device__ __forceinline__ void cp16(const void* smem_dst, const void* gsrc) {
    unsigned s = (unsigned)__cvta_generic_to_shared(smem_dst);
    asm volatile("cp.async.cg.shared.global [%0], [%1], 16;"
                 :: "r"(s), "l"(gsrc) : "memory");
}
#define CP_COMMIT() asm volatile("cp.async.commit_group;" ::: "memory")
#define CP_WAIT0()  asm volatile("cp.async.wait_group 0;"  ::: "memory")

__device__ __forceinline__ unsigned long long pk2(float x, float y) {
    unsigned long long r;
    asm("mov.b64 %0, {%1,%2};" : "=l"(r) : "f"(x), "f"(y));
    return r;
}
__device__ __forceinline__ float2 upk2(unsigned long long v) {
    float x, y;
    asm("mov.b64 {%0,%1}, %2;" : "=f"(x), "=f"(y) : "l"(v));
    return make_float2(x, y);
}
__device__ __forceinline__ unsigned long long fma2(unsigned long long a,
                                                   unsigned long long b,
                                                   unsigned long long c) {
    unsigned long long d;
    asm("fma.rn.f32x2 %0, %1, %2, %3;" : "=l"(d) : "l"(a), "l"(b), "l"(c));
    return d;
}

// ============================================================================
// one-time fp16 hi/lo split (lo scaled x32), packed half2 words
// ============================================================================
__global__ __launch_bounds__(256) void split_kernel(
    const float4* __restrict__ src, uint2* __restrict__ H, uint2* __restrict__ L)
{
    const int i = blockIdx.x * 256 + threadIdx.x;
    float4 v = src[i];
    __half hx = __float2half_rn(v.x), hy = __float2half_rn(v.y);
    __half hz = __float2half_rn(v.z), hw = __float2half_rn(v.w);
    uint2 h, l;
    h.x = pack_h2(__half2float(hx), __half2float(hy));
    h.y = pack_h2(__half2float(hz), __half2float(hw));
    l.x = pack_h2((v.x - __half2float(hx)) * LOSC, (v.y - __half2float(hy)) * LOSC);
    l.y = pack_h2((v.z - __half2float(hz)) * LOSC, (v.w - __half2float(hw)) * LOSC);
    H[i] = h; L[i] = l;
}

// ============================================================================
// 3-term fp16 GEMM (NT), cp.async double-buffered. BM=128,BN=64,BK=32(16w).
// Dynamic smem: sAh/sAl [2][128][20], sBh/sBl [2][64][20]  = 61440 B.
// ============================================================================
#define GST 20
#define GEMM_SMEM ((2*128*GST*2 + 2*64*GST*2) * 4)

__global__ __launch_bounds__(256, 2) void gemm_f16(
    const unsigned* __restrict__ Ah, const unsigned* __restrict__ Al,
    const unsigned* __restrict__ B0h, const unsigned* __restrict__ B0l,
    const unsigned* __restrict__ B1h, const unsigned* __restrict__ B1l,
    const unsigned* __restrict__ B2h, const unsigned* __restrict__ B2l,
    const float* __restrict__ b0p, const float* __restrict__ b1p,
    const float* __restrict__ b2p,
    float* __restrict__ C,
    unsigned* __restrict__ QH, unsigned* __restrict__ QL,
    unsigned* __restrict__ KH, unsigned* __restrict__ KL,
    __half* __restrict__ VtH, __half* __restrict__ VtL,
    int mode)
{
    const unsigned* Bh  = (blockIdx.z == 0) ? B0h : (blockIdx.z == 1) ? B1h : B2h;
    const unsigned* Bl  = (blockIdx.z == 0) ? B0l : (blockIdx.z == 1) ? B1l : B2l;
    const float*   bias = (blockIdx.z == 0) ? b0p : (blockIdx.z == 1) ? b1p : b2p;

    extern __shared__ unsigned smg[];
    unsigned* sAh = smg;                       // [2][128][GST]
    unsigned* sAl = sAh + 2 * 128 * GST;
    unsigned* sBh = sAl + 2 * 128 * GST;       // [2][64][GST]
    unsigned* sBl = sBh + 2 * 64 * GST;

    const int tid  = threadIdx.x;
    const int lane = tid & 31;
    const int wid  = tid >> 5;
    const int gID  = lane >> 2;
    const int tIG  = lane & 3;
    const int wm   = (wid >> 1) * 32;
    const int wn   = (wid & 1) * 32;
    const int m0   = blockIdx.y * 128;
    const int n0   = blockIdx.x * 64;

    auto prefetch = [&](int k0w, int bi) {
#pragma unroll
        for (int i = 0; i < 2; ++i) {
            int j = tid + i * 256;
            int row = j >> 2, wc = (j & 3) * 4;
            size_t ga = (size_t)(m0 + row) * WPR + k0w + wc;
            cp16(&sAh[bi * 128 * GST + row * GST + wc], Ah + ga);
            cp16(&sAl[bi * 128 * GST + row * GST + wc], Al + ga);
        }
        {
            int row = tid >> 2, wc = (tid & 3) * 4;
            size_t gb = (size_t)(n0 + row) * WPR + k0w + wc;
            cp16(&sBh[bi * 64 * GST + row * GST + wc], Bh + gb);
            cp16(&sBl[bi * 64 * GST + row * GST + wc], Bl + gb);
        }
    };

    float d[2][4][4], dc[2][4][4];
#pragma unroll
    for (int mi = 0; mi < 2; ++mi)
#pragma unroll
        for (int ni = 0; ni < 4; ++ni)
#pragma unroll
            for (int r = 0; r < 4; ++r) { d[mi][ni][r] = 0.f; dc[mi][ni][r] = 0.f; }

    prefetch(0, 0);
    CP_COMMIT();

    for (int it = 0; it < 16; ++it) {
        const int bi = it & 1;
        CP_WAIT0();
        __syncthreads();
        if (it + 1 < 16) { prefetch((it + 1) * 16, (it + 1) & 1); CP_COMMIT(); }

        const unsigned* cAh = sAh + bi * 128 * GST;
        const unsigned* cAl = sAl + bi * 128 * GST;
        const unsigned* cBh = sBh + bi * 64 * GST;
        const unsigned* cBl = sBl + bi * 64 * GST;

#pragma unroll
        for (int ks = 0; ks < 2; ++ks) {
            unsigned bh[4][2], bl[4][2];
#pragma unroll
            for (int ni = 0; ni < 4; ++ni) {
                const int rn = wn + ni * 8 + gID;
                bh[ni][0] = cBh[rn * GST + ks * 8 + tIG];
                bh[ni][1] = cBh[rn * GST + ks * 8 + tIG + 4];
                bl[ni][0] = cBl[rn * GST + ks * 8 + tIG];
                bl[ni][1] = cBl[rn * GST + ks * 8 + tIG + 4];
            }
#pragma unroll
            for (int mi = 0; mi < 2; ++mi) {
                const int ra = wm + mi * 16 + gID;
                unsigned ah[4], al[4];
                ah[0] = cAh[ra * GST       + ks * 8 + tIG];
                ah[1] = cAh[(ra + 8) * GST + ks * 8 + tIG];
                ah[2] = cAh[ra * GST       + ks * 8 + tIG + 4];
                ah[3] = cAh[(ra + 8) * GST + ks * 8 + tIG + 4];
                al[0] = cAl[ra * GST       + ks * 8 + tIG];
                al[1] = cAl[(ra + 8) * GST + ks * 8 + tIG];
                al[2] = cAl[ra * GST       + ks * 8 + tIG + 4];
                al[3] = cAl[(ra + 8) * GST + ks * 8 + tIG + 4];
#pragma unroll
                for (int ni = 0; ni < 4; ++ni) {
                    mma_f16(d [mi][ni], ah, bh[ni][0], bh[ni][1]);
                    mma_f16(dc[mi][ni], ah, bl[ni][0], bl[ni][1]);
                    mma_f16(dc[mi][ni], al, bh[ni][0], bh[ni][1]);
                }
            }
        }
    }

#pragma unroll
    for (int mi = 0; mi < 2; ++mi) {
#pragma unroll
        for (int ni = 0; ni < 4; ++ni) {
            const int row = m0 + wm + mi * 16 + gID;
            const int col = n0 + wn + ni * 8 + 2 * tIG;
            float2 bb = *(const float2*)&bias[col];
            float v00 = fmaf(dc[mi][ni][0], LOINV, d[mi][ni][0]) + bb.x;
            float v01 = fmaf(dc[mi][ni][1], LOINV, d[mi][ni][1]) + bb.y;
            float v10 = fmaf(dc[mi][ni][2], LOINV, d[mi][ni][2]) + bb.x;
            float v11 = fmaf(dc[mi][ni][3], LOINV, d[mi][ni][3]) + bb.y;
            if (mode == 1) {
                *(float2*)&C[(size_t)row * 512 + col]       = make_float2(v00, v01);
                *(float2*)&C[(size_t)(row + 8) * 512 + col] = make_float2(v10, v11);
            } else if (blockIdx.z < 2) {
                unsigned* H = (blockIdx.z == 0) ? QH : KH;
                unsigned* L = (blockIdx.z == 0) ? QL : KL;
                const float sc = (blockIdx.z == 0) ? 0.125f : 1.0f;
                v00 *= sc; v01 *= sc; v10 *= sc; v11 *= sc;
                __half h00 = __float2half_rn(v00), h01 = __float2half_rn(v01);
                __half h10 = __float2half_rn(v10), h11 = __float2half_rn(v11);
                const size_t w0 = (size_t)row * WPR + (col >> 1);
                const size_t w1 = (size_t)(row + 8) * WPR + (col >> 1);
                H[w0] = pack_h2(__half2float(h00), __half2float(h01));
                L[w0] = pack_h2((v00 - __half2float(h00)) * LOSC,
                                (v01 - __half2float(h01)) * LOSC);
                H[w1] = pack_h2(__half2float(h10), __half2float(h11));
                L[w1] = pack_h2((v10 - __half2float(h10)) * LOSC,
                                (v11 - __half2float(h11)) * LOSC);
            } else {
                float vv[4] = { v00, v01, v10, v11 };
#pragma unroll
                for (int u = 0; u < 4; ++u) {
                    const int rr = row + (u >> 1) * 8;
                    const int cc = col + (u & 1);
                    const int bidx = rr >> 10, tok = rr & 1023;
                    const int hh = cc >> 6, dd = cc & 63;
                    const size_t vi = (((size_t)bidx * HH + hh) * HD + dd) * NN + tok;
                    __half hv = __float2half_rn(vv[u]);
                    VtH[vi] = hv;
                    VtL[vi] = __float2half_rn(vv[u] - __half2float(hv));
                }
            }
        }
    }
}

// ============================================================================
// Edge bias (coalesced, smem-staged) — validated R6-R11. Side stream.
// ============================================================================
__global__ __launch_bounds__(256) void edge_bias_kernel(
    const float4* __restrict__ ef4, const int* __restrict__ mask,
    const float* __restrict__ We, const float* __restrict__ be,
    float* __restrict__ bias)
{
    __shared__ float sE[256 * 33];
    __shared__ unsigned long long sW2[EE][4];
    __shared__ float sbe[HH];

    const int t = threadIdx.x;
    if (t < EE * 4) {
        int e = t >> 2, p = t & 3;
        sW2[e][p] = pk2(We[(2 * p) * EE + e], We[(2 * p + 1) * EE + e]);
    }
    if (t < HH) sbe[t] = be[t];

    const size_t row0 = (size_t)blockIdx.x * 256;
    const size_t base4 = row0 * 8;

#pragma unroll
    for (int i = 0; i < 8; ++i) {
        int j = t + i * 256;
        float4 v = ef4[base4 + j];
        float* dst = &sE[(j >> 3) * 33 + (j & 7) * 4];
        dst[0] = v.x; dst[1] = v.y; dst[2] = v.z; dst[3] = v.w;
    }
    __syncthreads();

    const int mk = mask[row0 + t];

    unsigned long long acc[4];
#pragma unroll
    for (int p = 0; p < 4; ++p) acc[p] = pk2(sbe[2 * p], sbe[2 * p + 1]);

    const float* myrow = &sE[t * 33];
#pragma unroll
    for (int e = 0; e < EE; ++e) {
        float v = myrow[e];
        unsigned long long v2 = pk2(v, v);
#pragma unroll
        for (int p = 0; p < 4; ++p) acc[p] = fma2(v2, sW2[e][p], acc[p]);
    }

    const size_t kq = row0 + t;
    const int k = (int)(kq & (NN - 1));
    const size_t bq = kq >> 10;
    const int q = (int)(bq & (NN - 1));
    const int b = (int)(bq >> 10);

#pragma unroll
    for (int p = 0; p < 4; ++p) {
        float2 o = upk2(acc[p]);
        float o0 = mk ? o.x : -1e30f;
        float o1 = mk ? o.y : -1e30f;
        bias[(((size_t)b * HH + 2 * p    ) * NN + q) * NN + k] = o0;
        bias[(((size_t)b * HH + 2 * p + 1) * NN + q) * NN + k] = o1;
    }
}

// ============================================================================
// Flash attention (R10 math), cp.async double-buffered K/V/bias.
// Dynamic smem: K[2][32][36]x2, V[2][64][20]x2, B[2][64][36], P[64][20]
// = 62464 B -> 3 CTAs/SM.
// ============================================================================
#define KTILE 32
#define KSTW 36
#define VSTW 20
#define BSTW 36
#define ATTN_SMEM ((2*KTILE*KSTW*2 + 2*HD*VSTW*2 + 2*64*BSTW + 64*VSTW) * 4)

__global__ __launch_bounds__(128, 3) void attn_f16(
    const unsigned* __restrict__ QH, const unsigned* __restrict__ QL,
    const unsigned* __restrict__ KH, const unsigned* __restrict__ KL,
    const __half* __restrict__ VtH, const __half* __restrict__ VtL,
    const float* __restrict__ bias,
    unsigned* __restrict__ AOh, unsigned* __restrict__ AOl)
{
    extern __shared__ unsigned sma[];
    unsigned* sKh = sma;                        // [2][KTILE][KSTW]
    unsigned* sKl = sKh + 2 * KTILE * KSTW;
    unsigned* sVh = sKl + 2 * KTILE * KSTW;     // [2][HD][VSTW]
    unsigned* sVl = sVh + 2 * HD * VSTW;
    float*    sB  = (float*)(sVl + 2 * HD * VSTW);  // [2][64][BSTW]
    unsigned* sPh = (unsigned*)(sB + 2 * 64 * BSTW); // [64][VSTW]

    const int tid  = threadIdx.x;
    const int lane = tid & 31;
    const int wid  = tid >> 5;
    const int gID  = lane >> 2;
    const int tIG  = lane & 3;
    const int wq   = wid * 16;
    const int q0   = blockIdx.x * 64;
    const int h    = blockIdx.y;
    const int b    = blockIdx.z;

    const int rowA = wq + gID;
    const int rowB = wq + gID + 8;

    // ---- Q fragments in regs (hi + scaled lo) ----
    unsigned qh[4][4], ql[4][4];
    {
        const size_t rA = (size_t)(b * NN + q0 + rowA) * WPR + h * 32;
        const size_t rB = (size_t)(b * NN + q0 + rowB) * WPR + h * 32;
#pragma unroll
        for (int ks = 0; ks < 4; ++ks) {
            const int c = ks * 8 + tIG;
            qh[ks][0] = QH[rA + c];     qh[ks][1] = QH[rB + c];
            qh[ks][2] = QH[rA + c + 4]; qh[ks][3] = QH[rB + c + 4];
            ql[ks][0] = QL[rA + c];     ql[ks][1] = QL[rB + c];
            ql[ks][2] = QL[rA + c + 4]; ql[ks][3] = QL[rB + c + 4];
        }
    }

    const float* biasb = bias + ((size_t)b * HH + h) * NN * NN;
    const unsigned* VtHw = (const unsigned*)VtH;
    const unsigned* VtLw = (const unsigned*)VtL;
    const size_t vbase = ((size_t)b * HH + h) * HD * (NN / 2);

    auto prefetch = [&](int kt, int bi) {
#pragma unroll
        for (int i = 0; i < 2; ++i) {
            int j = tid + i * 128;
            int kr = j >> 3, wc = (j & 7) * 4;
            size_t gk = (size_t)(b * NN + kt + kr) * WPR + h * 32 + wc;
            cp16(&sKh[bi * KTILE * KSTW + kr * KSTW + wc], KH + gk);
            cp16(&sKl[bi * KTILE * KSTW + kr * KSTW + wc], KL + gk);
            int dr = j >> 2, vc = (j & 3) * 4;
            size_t gv = vbase + (size_t)dr * (NN / 2) + (kt >> 1) + vc;
            cp16(&sVh[bi * HD * VSTW + dr * VSTW + vc], VtHw + gv);
            cp16(&sVl[bi * HD * VSTW + dr * VSTW + vc], VtLw + gv);
        }
#pragma unroll
        for (int i = 0; i < 4; ++i) {
            int j = tid + i * 128;
            int brow = j >> 3, bc = (j & 7) * 4;
            cp16(&sB[bi * 64 * BSTW + brow * BSTW + bc],
                 biasb + (size_t)(q0 + brow) * NN + kt + bc);
        }
    };

    float m0 = -1e38f, m1 = -1e38f, l0 = 0.f, l1 = 0.f;
    float oacc[8][4];
#pragma unroll
    for (int ni = 0; ni < 8; ++ni)
#pragma unroll
        for (int r = 0; r < 4; ++r) oacc[ni][r] = 0.f;

    prefetch(0, 0);
    CP_COMMIT();

    for (int t = 0; t < NN / KTILE; ++t) {
        const int bi = t & 1;
        CP_WAIT0();
        __syncthreads();
        if (t + 1 < NN / KTILE) { prefetch((t + 1) * KTILE, (t + 1) & 1); CP_COMMIT(); }

        const unsigned* cKh = sKh + bi * KTILE * KSTW;
        const unsigned* cKl = sKl + bi * KTILE * KSTW;
        const unsigned* cVh = sVh + bi * HD * VSTW;
        const unsigned* cVl = sVl + bi * HD * VSTW;
        const float*    cB  = sB  + bi * 64 * BSTW;

        // ---- S = Q K^T (3-term; cross in separate acc) ----
        float sacc[4][4], scr[4][4];
#pragma unroll
        for (int ni = 0; ni < 4; ++ni)
#pragma unroll
            for (int r = 0; r < 4; ++r) { sacc[ni][r] = 0.f; scr[ni][r] = 0.f; }

#pragma unroll
        for (int ks = 0; ks < 4; ++ks) {
#pragma unroll
            for (int ni = 0; ni < 4; ++ni) {
                const int kr = ni * 8 + gID;
                unsigned kh0 = cKh[kr * KSTW + ks * 8 + tIG];
                unsigned kh1 = cKh[kr * KSTW + ks * 8 + tIG + 4];
                unsigned kl0 = cKl[kr * KSTW + ks * 8 + tIG];
                unsigned kl1 = cKl[kr * KSTW + ks * 8 + tIG + 4];
                mma_f16(sacc[ni], qh[ks], kh0, kh1);
                mma_f16(scr[ni],  qh[ks], kl0, kl1);
                mma_f16(scr[ni],  ql[ks], kh0, kh1);
            }
        }

        // ---- bias (smem) + online softmax ----
        float mx0 = -1e38f, mx1 = -1e38f;
#pragma unroll
        for (int ni = 0; ni < 4; ++ni) {
            float2 b0v = *(const float2*)&cB[rowA * BSTW + ni * 8 + 2 * tIG];
            float2 b1v = *(const float2*)&cB[rowB * BSTW + ni * 8 + 2 * tIG];
            sacc[ni][0] = fmaf(scr[ni][0], LOINV, sacc[ni][0]) + b0v.x;
            sacc[ni][1] = fmaf(scr[ni][1], LOINV, sacc[ni][1]) + b0v.y;
            sacc[ni][2] = fmaf(scr[ni][2], LOINV, sacc[ni][2]) + b1v.x;
            sacc[ni][3] = fmaf(scr[ni][3], LOINV, sacc[ni][3]) + b1v.y;
            mx0 = fmaxf(mx0, fmaxf(sacc[ni][0], sacc[ni][1]));
            mx1 = fmaxf(mx1, fmaxf(sacc[ni][2], sacc[ni][3]));
        }
        mx0 = fmaxf(mx0, __shfl_xor_sync(0xffffffffu, mx0, 1));
        mx0 = fmaxf(mx0, __shfl_xor_sync(0xffffffffu, mx0, 2));
        mx1 = fmaxf(mx1, __shfl_xor_sync(0xffffffffu, mx1, 1));
        mx1 = fmaxf(mx1, __shfl_xor_sync(0xffffffffu, mx1, 2));

        const float mn0 = fmaxf(m0, mx0), mn1 = fmaxf(m1, mx1);
        const float c0f = __expf(m0 - mn0), c1f = __expf(m1 - mn1);
        m0 = mn0; m1 = mn1;

        float ps0 = 0.f, ps1 = 0.f;
#pragma unroll
        for (int ni = 0; ni < 4; ++ni) {
            sacc[ni][0] = __expf(sacc[ni][0] - mn0); ps0 += sacc[ni][0];
            sacc[ni][1] = __expf(sacc[ni][1] - mn0); ps0 += sacc[ni][1];
            sacc[ni][2] = __expf(sacc[ni][2] - mn1); ps1 += sacc[ni][2];
            sacc[ni][3] = __expf(sacc[ni][3] - mn1); ps1 += sacc[ni][3];
        }
        ps0 += __shfl_xor_sync(0xffffffffu, ps0, 1);
        ps0 += __shfl_xor_sync(0xffffffffu, ps0, 2);
        ps1 += __shfl_xor_sync(0xffffffffu, ps1, 1);
        ps1 += __shfl_xor_sync(0xffffffffu, ps1, 2);
        l0 = l0 * c0f + ps0;
        l1 = l1 * c1f + ps1;

#pragma unroll
        for (int ni = 0; ni < 8; ++ni) {
            oacc[ni][0] *= c0f; oacc[ni][1] *= c0f;
            oacc[ni][2] *= c1f; oacc[ni][3] *= c1f;
        }

        // ---- P -> fp16 (1-term), warp-private smem rows ----
#pragma unroll
        for (int ni = 0; ni < 4; ++ni) {
            sPh[rowA * VSTW + ni * 4 + tIG] = pack_h2(sacc[ni][0], sacc[ni][1]);
            sPh[rowB * VSTW + ni * 4 + tIG] = pack_h2(sacc[ni][2], sacc[ni][3]);
        }
        __syncwarp();

        // ---- O += P V (P 1-term, V 2-term) ----
#pragma unroll
        for (int ks = 0; ks < 2; ++ks) {
            unsigned ph[4];
            ph[0] = sPh[rowA * VSTW + ks * 8 + tIG];
            ph[1] = sPh[rowB * VSTW + ks * 8 + tIG];
            ph[2] = sPh[rowA * VSTW + ks * 8 + tIG + 4];
            ph[3] = sPh[rowB * VSTW + ks * 8 + tIG + 4];
#pragma unroll
            for (int ni = 0; ni < 8; ++ni) {
                const int dr = ni * 8 + gID;
                unsigned vh0 = cVh[dr * VSTW + ks * 8 + tIG];
                unsigned vh1 = cVh[dr * VSTW + ks * 8 + tIG + 4];
                unsigned vl0 = cVl[dr * VSTW + ks * 8 + tIG];
                unsigned vl1 = cVl[dr * VSTW + ks * 8 + tIG + 4];
                mma_f16(oacc[ni], ph, vh0, vh1);
                mma_f16(oacc[ni], ph, vl0, vl1);
            }
        }
    }

    // ---- epilogue: normalize + split, write AO hi / lo(x32) words ----
    const float i0 = 1.0f / l0, i1 = 1.0f / l1;
    const size_t oa = (size_t)(b * NN + q0 + rowA) * WPR + h * 32;
    const size_t ob = (size_t)(b * NN + q0 + rowB) * WPR + h * 32;
#pragma unroll
    for (int ni = 0; ni < 8; ++ni) {
        const int w = ni * 4 + tIG;
        float v0 = oacc[ni][0] * i0, v1 = oacc[ni][1] * i0;
        float v2 = oacc[ni][2] * i1, v3 = oacc[ni][3] * i1;
        __half h0 = __float2half_rn(v0), h1 = __float2half_rn(v1);
        __half h2 = __float2half_rn(v2), h3 = __float2half_rn(v3);
        AOh[oa + w] = pack_h2(__half2float(h0), __half2float(h1));
        AOl[oa + w] = pack_h2((v0 - __half2float(h0)) * LOSC,
                              (v1 - __half2float(h1)) * LOSC);
        AOh[ob + w] = pack_h2(__half2float(h2), __half2float(h3));
        AOl[ob + w] = pack_h2((v2 - __half2float(h2)) * LOSC,
                              (v3 - __half2float(h3)) * LOSC);
    }
}

// ============================================================================
// Launch — edge bias on side stream; pipelined GEMM/attn with dynamic smem.
// ============================================================================
extern "C" void kernel_launch(void* const* d_in, const int* in_sizes, int n_in,
                              void* d_out, int out_size)
{
    (void)in_sizes; (void)n_in; (void)out_size;
    const float* x   = (const float*)d_in[0];
    const float* ef  = (const float*)d_in[1];
    const int*   msk = (const int*)  d_in[2];
    const float* Wq  = (const float*)d_in[3];
    const float* bq  = (const float*)d_in[4];
    const float* Wk  = (const float*)d_in[5];
    const float* bk  = (const float*)d_in[6];
    const float* Wv  = (const float*)d_in[7];
    const float* bv  = (const float*)d_in[8];
    const float* We  = (const float*)d_in[9];
    const float* be  = (const float*)d_in[10];
    const float* Wo  = (const float*)d_in[11];
    const float* bo  = (const float*)d_in[12];
    float* out = (float*)d_out;

    unsigned *pxh, *pxl, *pWqh, *pWql, *pWkh, *pWkl, *pWvh, *pWvl, *pWoh, *pWol;
    unsigned *pQh, *pQl, *pKh, *pKl, *pAOh, *pAOl;
    __half *pVth, *pVtl;
    float *pBias;
    cudaGetSymbolAddress((void**)&pxh,  g_xh);  cudaGetSymbolAddress((void**)&pxl,  g_xl);
    cudaGetSymbolAddress((void**)&pWqh, g_Wqh); cudaGetSymbolAddress((void**)&pWql, g_Wql);
    cudaGetSymbolAddress((void**)&pWkh, g_Wkh); cudaGetSymbolAddress((void**)&pWkl, g_Wkl);
    cudaGetSymbolAddress((void**)&pWvh, g_Wvh); cudaGetSymbolAddress((void**)&pWvl, g_Wvl);
    cudaGetSymbolAddress((void**)&pWoh, g_Woh); cudaGetSymbolAddress((void**)&pWol, g_Wol);
    cudaGetSymbolAddress((void**)&pQh,  g_Qh);  cudaGetSymbolAddress((void**)&pQl,  g_Ql);
    cudaGetSymbolAddress((void**)&pKh,  g_Kh);  cudaGetSymbolAddress((void**)&pKl,  g_Kl);
    cudaGetSymbolAddress((void**)&pVth, g_Vth); cudaGetSymbolAddress((void**)&pVtl, g_Vtl);
    cudaGetSymbolAddress((void**)&pAOh, g_AOh); cudaGetSymbolAddress((void**)&pAOl, g_AOl);
    cudaGetSymbolAddress((void**)&pBias, g_bias);

    static cudaStream_t s_edge = nullptr;
    static cudaEvent_t ev_fork = nullptr, ev_join = nullptr;
    if (!s_edge) {
        cudaStreamCreateWithFlags(&s_edge, cudaStreamNonBlocking);
        cudaEventCreateWithFlags(&ev_fork, cudaEventDisableTiming);
        cudaEventCreateWithFlags(&ev_join, cudaEventDisableTiming);
        cudaFuncSetAttribute(gemm_f16, cudaFuncAttributeMaxDynamicSharedMemorySize,
                             GEMM_SMEM);
        cudaFuncSetAttribute(attn_f16, cudaFuncAttributeMaxDynamicSharedMemorySize,
                             ATTN_SMEM);
    }

    // ---- fork: edge bias (pure DRAM) concurrent with splits + QKV ----
    cudaEventRecord(ev_fork, 0);
    cudaStreamWaitEvent(s_edge, ev_fork, 0);
    edge_bias_kernel<<<(BB * NN * NN) / 256, 256, 0, s_edge>>>(
        (const float4*)ef, msk, We, be, pBias);
    cudaEventRecord(ev_join, s_edge);

    // ---- main chain: splits -> QKV ----
    split_kernel<<<(MM * FF / 4) / 256, 256>>>((const float4*)x,  (uint2*)pxh,  (uint2*)pxl);
    split_kernel<<<(FF * FF / 4) / 256, 256>>>((const float4*)Wq, (uint2*)pWqh, (uint2*)pWql);
    split_kernel<<<(FF * FF / 4) / 256, 256>>>((const float4*)Wk, (uint2*)pWkh, (uint2*)pWkl);
    split_kernel<<<(FF * FF / 4) / 256, 256>>>((const float4*)Wv, (uint2*)pWvh, (uint2*)pWvl);
    split_kernel<<<(FF * FF / 4) / 256, 256>>>((const float4*)Wo, (uint2*)pWoh, (uint2*)pWol);

    dim3 gqkv(512 / 64, MM / 128, 3);
    gemm_f16<<<gqkv, 256, GEMM_SMEM>>>(pxh, pxl,
                            pWqh, pWql, pWkh, pWkl, pWvh, pWvl,
                            bq, bk, bv,
                            nullptr, pQh, pQl, pKh, pKl, pVth, pVtl, 0);

    cudaStreamWaitEvent(0, ev_join, 0);

    attn_f16<<<dim3(NN / 64, HH, BB), 128, ATTN_SMEM>>>(
        pQh, pQl, pKh, pKl, pVth, pVtl, pBias, pAOh, pAOl);

    dim3 go(512 / 64, MM / 128, 1);
    gemm_f16<<<go, 256, GEMM_SMEM>>>(pAOh, pAOl,
                          pWoh, pWol, pWoh, pWol, pWoh, pWol,
                          bo, bo, bo,
                          out, nullptr, nullptr, nullptr, nullptr,
                          nullptr, nullptr, 1);
}

// round 13
// speedup vs baseline: 1.9112x; 1.0445x over previous
#include <cuda_runtime.h>
#include <cuda_fp16.h>
#include <math.h>

#define BB 4
#define NN 1024
#define FF 512
#define EE 32
#define HH 8
#define HD 64
#define MM (BB*NN)     // 4096
#define WPR 256        // half2 words per 512-float row
#define LOSC 32.0f
#define LOINV 0.03125f

// ---- scratch (static device globals; runtime alloc is forbidden) ----
__device__ unsigned g_xh [MM*WPR], g_xl [MM*WPR];
__device__ unsigned g_Wqh[FF*WPR], g_Wql[FF*WPR];
__device__ unsigned g_Wkh[FF*WPR], g_Wkl[FF*WPR];
__device__ unsigned g_Wvh[FF*WPR], g_Wvl[FF*WPR];
__device__ unsigned g_Woh[FF*WPR], g_Wol[FF*WPR];
__device__ unsigned g_Qh [MM*WPR], g_Ql [MM*WPR];   // lo scaled x32
__device__ unsigned g_Kh [MM*WPR], g_Kl [MM*WPR];   // lo scaled x32
__device__ __half   g_Vth[(size_t)BB*HH*HD*NN];     // V transposed [b][h][d][tok]
__device__ __half   g_Vtl[(size_t)BB*HH*HD*NN];     // lo UNSCALED
__device__ unsigned g_AOh[MM*WPR], g_AOl[MM*WPR];   // lo scaled x32
__device__ __half   g_bias[(size_t)BB*HH*NN*NN];    // fp16 bias, mask folded (-60000)

// ============================================================================
// helpers
// ============================================================================
__device__ __forceinline__ unsigned pack_h2(float a, float b) {
    __half2 h = __floats2half2_rn(a, b);
    return *reinterpret_cast<unsigned*>(&h);
}

__device__ __forceinline__ void mma_f16(float (&d)[4], const unsigned (&a)[4],
                                        unsigned b0, unsigned b1) {
    asm volatile(
        "mma.sync.aligned.m16n8k16.row.col.f32.f16.f16.f32 "
        "{%0,%1,%2,%3}, {%4,%5,%6,%7}, {%8,%9}, {%0,%1,%2,%3};\n"
        : "+f"(d[0]), "+f"(d[1]), "+f"(d[2]), "+f"(d[3])
        : "r"(a[0]), "r"(a[1]), "r"(a[2]), "r"(a[3]), "r"(b0), "r"(b1));
}

__device__ __forceinline__ void cp16(const void* smem_dst, const void* gsrc) {
    unsigned s = (unsigned)__cvta_generic_to_shared(smem_dst);
    asm volatile("cp.async.cg.shared.global [%0], [%1], 16;"
                 :: "r"(s), "l"(gsrc) : "memory");
}
#define CP_COMMIT() asm volatile("cp.async.commit_group;" ::: "memory")
#define CP_WAIT0()  asm volatile("cp.async.wait_group 0;"  ::: "memory")

__device__ __forceinline__ unsigned long long pk2(float x, float y) {
    unsigned long long r;
    asm("mov.b64 %0, {%1,%2};" : "=l"(r) : "f"(x), "f"(y));
    return r;
}
__device__ __forceinline__ float2 upk2(unsigned long long v) {
    float x, y;
    asm("mov.b64 {%0,%1}, %2;" : "=f"(x), "=f"(y) : "l"(v));
    return make_float2(x, y);
}
__device__ __forceinline__ unsigned long long fma2(unsigned long long a,
                                                   unsigned long long b,
                                                   unsigned long long c) {
    unsigned long long d;
    asm("fma.rn.f32x2 %0, %1, %2, %3;" : "=l"(d) : "l"(a), "l"(b), "l"(c));
    return d;
}

// ============================================================================
// one-time fp16 hi/lo splits (lo scaled x32), packed half2 words
// ============================================================================
__global__ __launch_bounds__(256) void split_kernel(
    const float4* __restrict__ src, uint2* __restrict__ H, uint2* __restrict__ L)
{
    const int i = blockIdx.x * 256 + threadIdx.x;
    float4 v = src[i];
    __half hx = __float2half_rn(v.x), hy = __float2half_rn(v.y);
    __half hz = __float2half_rn(v.z), hw = __float2half_rn(v.w);
    uint2 h, l;
    h.x = pack_h2(__half2float(hx), __half2float(hy));
    h.y = pack_h2(__half2float(hz), __half2float(hw));
    l.x = pack_h2((v.x - __half2float(hx)) * LOSC, (v.y - __half2float(hy)) * LOSC);
    l.y = pack_h2((v.z - __half2float(hz)) * LOSC, (v.w - __half2float(hw)) * LOSC);
    H[i] = h; L[i] = l;
}

// two weight matrices per launch (blockIdx.y selects)
__global__ __launch_bounds__(256) void split2_kernel(
    const float4* __restrict__ srcA, uint2* __restrict__ HA, uint2* __restrict__ LA,
    const float4* __restrict__ srcB, uint2* __restrict__ HB, uint2* __restrict__ LB)
{
    const float4* src = blockIdx.y ? srcB : srcA;
    uint2* H = blockIdx.y ? HB : HA;
    uint2* L = blockIdx.y ? LB : LA;
    const int i = blockIdx.x * 256 + threadIdx.x;
    float4 v = src[i];
    __half hx = __float2half_rn(v.x), hy = __float2half_rn(v.y);
    __half hz = __float2half_rn(v.z), hw = __float2half_rn(v.w);
    uint2 h, l;
    h.x = pack_h2(__half2float(hx), __half2float(hy));
    h.y = pack_h2(__half2float(hz), __half2float(hw));
    l.x = pack_h2((v.x - __half2float(hx)) * LOSC, (v.y - __half2float(hy)) * LOSC);
    l.y = pack_h2((v.z - __half2float(hz)) * LOSC, (v.w - __half2float(hw)) * LOSC);
    H[i] = h; L[i] = l;
}

// ============================================================================
// 3-term fp16 GEMM (NT), cp.async double-buffered — validated R12.
// ============================================================================
#define GST 20
#define GEMM_SMEM ((2*128*GST*2 + 2*64*GST*2) * 4)

__global__ __launch_bounds__(256, 2) void gemm_f16(
    const unsigned* __restrict__ Ah, const unsigned* __restrict__ Al,
    const unsigned* __restrict__ B0h, const unsigned* __restrict__ B0l,
    const unsigned* __restrict__ B1h, const unsigned* __restrict__ B1l,
    const unsigned* __restrict__ B2h, const unsigned* __restrict__ B2l,
    const float* __restrict__ b0p, const float* __restrict__ b1p,
    const float* __restrict__ b2p,
    float* __restrict__ C,
    unsigned* __restrict__ QH, unsigned* __restrict__ QL,
    unsigned* __restrict__ KH, unsigned* __restrict__ KL,
    __half* __restrict__ VtH, __half* __restrict__ VtL,
    int mode)
{
    const unsigned* Bh  = (blockIdx.z == 0) ? B0h : (blockIdx.z == 1) ? B1h : B2h;
    const unsigned* Bl  = (blockIdx.z == 0) ? B0l : (blockIdx.z == 1) ? B1l : B2l;
    const float*   bias = (blockIdx.z == 0) ? b0p : (blockIdx.z == 1) ? b1p : b2p;

    extern __shared__ unsigned smg[];
    unsigned* sAh = smg;
    unsigned* sAl = sAh + 2 * 128 * GST;
    unsigned* sBh = sAl + 2 * 128 * GST;
    unsigned* sBl = sBh + 2 * 64 * GST;

    const int tid  = threadIdx.x;
    const int lane = tid & 31;
    const int wid  = tid >> 5;
    const int gID  = lane >> 2;
    const int tIG  = lane & 3;
    const int wm   = (wid >> 1) * 32;
    const int wn   = (wid & 1) * 32;
    const int m0   = blockIdx.y * 128;
    const int n0   = blockIdx.x * 64;

    auto prefetch = [&](int k0w, int bi) {
#pragma unroll
        for (int i = 0; i < 2; ++i) {
            int j = tid + i * 256;
            int row = j >> 2, wc = (j & 3) * 4;
            size_t ga = (size_t)(m0 + row) * WPR + k0w + wc;
            cp16(&sAh[bi * 128 * GST + row * GST + wc], Ah + ga);
            cp16(&sAl[bi * 128 * GST + row * GST + wc], Al + ga);
        }
        {
            int row = tid >> 2, wc = (tid & 3) * 4;
            size_t gb = (size_t)(n0 + row) * WPR + k0w + wc;
            cp16(&sBh[bi * 64 * GST + row * GST + wc], Bh + gb);
            cp16(&sBl[bi * 64 * GST + row * GST + wc], Bl + gb);
        }
    };

    float d[2][4][4], dc[2][4][4];
#pragma unroll
    for (int mi = 0; mi < 2; ++mi)
#pragma unroll
        for (int ni = 0; ni < 4; ++ni)
#pragma unroll
            for (int r = 0; r < 4; ++r) { d[mi][ni][r] = 0.f; dc[mi][ni][r] = 0.f; }

    prefetch(0, 0);
    CP_COMMIT();

    for (int it = 0; it < 16; ++it) {
        const int bi = it & 1;
        CP_WAIT0();
        __syncthreads();
        if (it + 1 < 16) { prefetch((it + 1) * 16, (it + 1) & 1); CP_COMMIT(); }

        const unsigned* cAh = sAh + bi * 128 * GST;
        const unsigned* cAl = sAl + bi * 128 * GST;
        const unsigned* cBh = sBh + bi * 64 * GST;
        const unsigned* cBl = sBl + bi * 64 * GST;

#pragma unroll
        for (int ks = 0; ks < 2; ++ks) {
            unsigned bh[4][2], bl[4][2];
#pragma unroll
            for (int ni = 0; ni < 4; ++ni) {
                const int rn = wn + ni * 8 + gID;
                bh[ni][0] = cBh[rn * GST + ks * 8 + tIG];
                bh[ni][1] = cBh[rn * GST + ks * 8 + tIG + 4];
                bl[ni][0] = cBl[rn * GST + ks * 8 + tIG];
                bl[ni][1] = cBl[rn * GST + ks * 8 + tIG + 4];
            }
#pragma unroll
            for (int mi = 0; mi < 2; ++mi) {
                const int ra = wm + mi * 16 + gID;
                unsigned ah[4], al[4];
                ah[0] = cAh[ra * GST       + ks * 8 + tIG];
                ah[1] = cAh[(ra + 8) * GST + ks * 8 + tIG];
                ah[2] = cAh[ra * GST       + ks * 8 + tIG + 4];
                ah[3] = cAh[(ra + 8) * GST + ks * 8 + tIG + 4];
                al[0] = cAl[ra * GST       + ks * 8 + tIG];
                al[1] = cAl[(ra + 8) * GST + ks * 8 + tIG];
                al[2] = cAl[ra * GST       + ks * 8 + tIG + 4];
                al[3] = cAl[(ra + 8) * GST + ks * 8 + tIG + 4];
#pragma unroll
                for (int ni = 0; ni < 4; ++ni) {
                    mma_f16(d [mi][ni], ah, bh[ni][0], bh[ni][1]);
                    mma_f16(dc[mi][ni], ah, bl[ni][0], bl[ni][1]);
                    mma_f16(dc[mi][ni], al, bh[ni][0], bh[ni][1]);
                }
            }
        }
    }

#pragma unroll
    for (int mi = 0; mi < 2; ++mi) {
#pragma unroll
        for (int ni = 0; ni < 4; ++ni) {
            const int row = m0 + wm + mi * 16 + gID;
            const int col = n0 + wn + ni * 8 + 2 * tIG;
            float2 bb = *(const float2*)&bias[col];
            float v00 = fmaf(dc[mi][ni][0], LOINV, d[mi][ni][0]) + bb.x;
            float v01 = fmaf(dc[mi][ni][1], LOINV, d[mi][ni][1]) + bb.y;
            float v10 = fmaf(dc[mi][ni][2], LOINV, d[mi][ni][2]) + bb.x;
            float v11 = fmaf(dc[mi][ni][3], LOINV, d[mi][ni][3]) + bb.y;
            if (mode == 1) {
                *(float2*)&C[(size_t)row * 512 + col]       = make_float2(v00, v01);
                *(float2*)&C[(size_t)(row + 8) * 512 + col] = make_float2(v10, v11);
            } else if (blockIdx.z < 2) {
                unsigned* H = (blockIdx.z == 0) ? QH : KH;
                unsigned* L = (blockIdx.z == 0) ? QL : KL;
                const float sc = (blockIdx.z == 0) ? 0.125f : 1.0f;
                v00 *= sc; v01 *= sc; v10 *= sc; v11 *= sc;
                __half h00 = __float2half_rn(v00), h01 = __float2half_rn(v01);
                __half h10 = __float2half_rn(v10), h11 = __float2half_rn(v11);
                const size_t w0 = (size_t)row * WPR + (col >> 1);
                const size_t w1 = (size_t)(row + 8) * WPR + (col >> 1);
                H[w0] = pack_h2(__half2float(h00), __half2float(h01));
                L[w0] = pack_h2((v00 - __half2float(h00)) * LOSC,
                                (v01 - __half2float(h01)) * LOSC);
                H[w1] = pack_h2(__half2float(h10), __half2float(h11));
                L[w1] = pack_h2((v10 - __half2float(h10)) * LOSC,
                                (v11 - __half2float(h11)) * LOSC);
            } else {
                float vv[4] = { v00, v01, v10, v11 };
#pragma unroll
                for (int u = 0; u < 4; ++u) {
                    const int rr = row + (u >> 1) * 8;
                    const int cc = col + (u & 1);
                    const int bidx = rr >> 10, tok = rr & 1023;
                    const int hh = cc >> 6, dd = cc & 63;
                    const size_t vi = (((size_t)bidx * HH + hh) * HD + dd) * NN + tok;
                    __half hv = __float2half_rn(vv[u]);
                    VtH[vi] = hv;
                    VtL[vi] = __float2half_rn(vv[u] - __half2float(hv));
                }
            }
        }
    }
}

// ============================================================================
// Edge bias -> fp16 output (mask folded as -60000). Side stream.
// ============================================================================
__global__ __launch_bounds__(256) void edge_bias_kernel(
    const float4* __restrict__ ef4, const int* __restrict__ mask,
    const float* __restrict__ We, const float* __restrict__ be,
    __half* __restrict__ bias)
{
    __shared__ float sE[256 * 33];
    __shared__ unsigned long long sW2[EE][4];
    __shared__ float sbe[HH];

    const int t = threadIdx.x;
    if (t < EE * 4) {
        int e = t >> 2, p = t & 3;
        sW2[e][p] = pk2(We[(2 * p) * EE + e], We[(2 * p + 1) * EE + e]);
    }
    if (t < HH) sbe[t] = be[t];

    const size_t row0 = (size_t)blockIdx.x * 256;
    const size_t base4 = row0 * 8;

#pragma unroll
    for (int i = 0; i < 8; ++i) {
        int j = t + i * 256;
        float4 v = ef4[base4 + j];
        float* dst = &sE[(j >> 3) * 33 + (j & 7) * 4];
        dst[0] = v.x; dst[1] = v.y; dst[2] = v.z; dst[3] = v.w;
    }
    __syncthreads();

    const int mk = mask[row0 + t];

    unsigned long long acc[4];
#pragma unroll
    for (int p = 0; p < 4; ++p) acc[p] = pk2(sbe[2 * p], sbe[2 * p + 1]);

    const float* myrow = &sE[t * 33];
#pragma unroll
    for (int e = 0; e < EE; ++e) {
        float v = myrow[e];
        unsigned long long v2 = pk2(v, v);
#pragma unroll
        for (int p = 0; p < 4; ++p) acc[p] = fma2(v2, sW2[e][p], acc[p]);
    }

    const size_t kq = row0 + t;
    const int k = (int)(kq & (NN - 1));
    const size_t bq = kq >> 10;
    const int q = (int)(bq & (NN - 1));
    const int b = (int)(bq >> 10);

#pragma unroll
    for (int p = 0; p < 4; ++p) {
        float2 o = upk2(acc[p]);
        float o0 = mk ? o.x : -60000.0f;
        float o1 = mk ? o.y : -60000.0f;
        bias[(((size_t)b * HH + 2 * p    ) * NN + q) * NN + k] = __float2half_rn(o0);
        bias[(((size_t)b * HH + 2 * p + 1) * NN + q) * NN + k] = __float2half_rn(o1);
    }
}

// ============================================================================
// Flash attention (R12 pipeline) with fp16 bias; 4 CTAs/SM.
// Dynamic smem: K[2][32][36]x2 + V[2][64][20]x2 + Bh2[2][64][20] + P[64][20]
// = 54272 B.
// ============================================================================
#define KTILE 32
#define KSTW 36
#define VSTW 20
#define BSTW 20    // bias tile stride in half2 WORDS (16 data + 4 pad)
#define ATTN_SMEM ((2*KTILE*KSTW*2 + 2*HD*VSTW*2 + 2*64*BSTW + 64*VSTW) * 4)

__global__ __launch_bounds__(128, 4) void attn_f16(
    const unsigned* __restrict__ QH, const unsigned* __restrict__ QL,
    const unsigned* __restrict__ KH, const unsigned* __restrict__ KL,
    const __half* __restrict__ VtH, const __half* __restrict__ VtL,
    const __half* __restrict__ bias,
    unsigned* __restrict__ AOh, unsigned* __restrict__ AOl)
{
    extern __shared__ unsigned sma[];
    unsigned* sKh = sma;
    unsigned* sKl = sKh + 2 * KTILE * KSTW;
    unsigned* sVh = sKl + 2 * KTILE * KSTW;
    unsigned* sVl = sVh + 2 * HD * VSTW;
    unsigned* sB  = sVl + 2 * HD * VSTW;        // [2][64][BSTW] half2 words
    unsigned* sPh = sB + 2 * 64 * BSTW;         // [64][VSTW]

    const int tid  = threadIdx.x;
    const int lane = tid & 31;
    const int wid  = tid >> 5;
    const int gID  = lane >> 2;
    const int tIG  = lane & 3;
    const int wq   = wid * 16;
    const int q0   = blockIdx.x * 64;
    const int h    = blockIdx.y;
    const int b    = blockIdx.z;

    const int rowA = wq + gID;
    const int rowB = wq + gID + 8;

    // ---- Q fragments in regs (hi + scaled lo) ----
    unsigned qh[4][4], ql[4][4];
    {
        const size_t rA = (size_t)(b * NN + q0 + rowA) * WPR + h * 32;
        const size_t rB = (size_t)(b * NN + q0 + rowB) * WPR + h * 32;
#pragma unroll
        for (int ks = 0; ks < 4; ++ks) {
            const int c = ks * 8 + tIG;
            qh[ks][0] = QH[rA + c];     qh[ks][1] = QH[rB + c];
            qh[ks][2] = QH[rA + c + 4]; qh[ks][3] = QH[rB + c + 4];
            ql[ks][0] = QL[rA + c];     ql[ks][1] = QL[rB + c];
            ql[ks][2] = QL[rA + c + 4]; ql[ks][3] = QL[rB + c + 4];
        }
    }

    const __half* biasb = bias + ((size_t)b * HH + h) * NN * NN;
    const unsigned* VtHw = (const unsigned*)VtH;
    const unsigned* VtLw = (const unsigned*)VtL;
    const size_t vbase = ((size_t)b * HH + h) * HD * (NN / 2);

    auto prefetch = [&](int kt, int bi) {
#pragma unroll
        for (int i = 0; i < 2; ++i) {
            int j = tid + i * 128;
            int kr = j >> 3, wc = (j & 7) * 4;
            size_t gk = (size_t)(b * NN + kt + kr) * WPR + h * 32 + wc;
            cp16(&sKh[bi * KTILE * KSTW + kr * KSTW + wc], KH + gk);
            cp16(&sKl[bi * KTILE * KSTW + kr * KSTW + wc], KL + gk);
            int dr = j >> 2, vc = (j & 3) * 4;
            size_t gv = vbase + (size_t)dr * (NN / 2) + (kt >> 1) + vc;
            cp16(&sVh[bi * HD * VSTW + dr * VSTW + vc], VtHw + gv);
            cp16(&sVl[bi * HD * VSTW + dr * VSTW + vc], VtLw + gv);
            // bias tile: 64 rows x 16 half2 words -> 256 16B chunks
            int brow = j >> 2, bc = (j & 3) * 4;     // word offset
            cp16(&sB[bi * 64 * BSTW + brow * BSTW + bc],
                 biasb + (size_t)(q0 + brow) * NN + kt + bc * 2);
        }
    };

    float m0 = -1e38f, m1 = -1e38f, l0 = 0.f, l1 = 0.f;
    float oacc[8][4];
#pragma unroll
    for (int ni = 0; ni < 8; ++ni)
#pragma unroll
        for (int r = 0; r < 4; ++r) oacc[ni][r] = 0.f;

    prefetch(0, 0);
    CP_COMMIT();

    for (int t = 0; t < NN / KTILE; ++t) {
        const int bi = t & 1;
        CP_WAIT0();
        __syncthreads();
        if (t + 1 < NN / KTILE) { prefetch((t + 1) * KTILE, (t + 1) & 1); CP_COMMIT(); }

        const unsigned* cKh = sKh + bi * KTILE * KSTW;
        const unsigned* cKl = sKl + bi * KTILE * KSTW;
        const unsigned* cVh = sVh + bi * HD * VSTW;
        const unsigned* cVl = sVl + bi * HD * VSTW;
        const unsigned* cB  = sB  + bi * 64 * BSTW;

        // ---- S = Q K^T (3-term; cross in separate acc) ----
        float sacc[4][4], scr[4][4];
#pragma unroll
        for (int ni = 0; ni < 4; ++ni)
#pragma unroll
            for (int r = 0; r < 4; ++r) { sacc[ni][r] = 0.f; scr[ni][r] = 0.f; }

#pragma unroll
        for (int ks = 0; ks < 4; ++ks) {
#pragma unroll
            for (int ni = 0; ni < 4; ++ni) {
                const int kr = ni * 8 + gID;
                unsigned kh0 = cKh[kr * KSTW + ks * 8 + tIG];
                unsigned kh1 = cKh[kr * KSTW + ks * 8 + tIG + 4];
                unsigned kl0 = cKl[kr * KSTW + ks * 8 + tIG];
                unsigned kl1 = cKl[kr * KSTW + ks * 8 + tIG + 4];
                mma_f16(sacc[ni], qh[ks], kh0, kh1);
                mma_f16(scr[ni],  qh[ks], kl0, kl1);
                mma_f16(scr[ni],  ql[ks], kh0, kh1);
            }
        }

        // ---- bias (fp16 smem) + online softmax ----
        float mx0 = -1e38f, mx1 = -1e38f;
#pragma unroll
        for (int ni = 0; ni < 4; ++ni) {
            unsigned w0 = cB[rowA * BSTW + ni * 4 + tIG];
            unsigned w1 = cB[rowB * BSTW + ni * 4 + tIG];
            float2 b0v = __half22float2(*reinterpret_cast<__half2*>(&w0));
            float2 b1v = __half22float2(*reinterpret_cast<__half2*>(&w1));
            sacc[ni][0] = fmaf(scr[ni][0], LOINV, sacc[ni][0]) + b0v.x;
            sacc[ni][1] = fmaf(scr[ni][1], LOINV, sacc[ni][1]) + b0v.y;
            sacc[ni][2] = fmaf(scr[ni][2], LOINV, sacc[ni][2]) + b1v.x;
            sacc[ni][3] = fmaf(scr[ni][3], LOINV, sacc[ni][3]) + b1v.y;
            mx0 = fmaxf(mx0, fmaxf(sacc[ni][0], sacc[ni][1]));
            mx1 = fmaxf(mx1, fmaxf(sacc[ni][2], sacc[ni][3]));
        }
        mx0 = fmaxf(mx0, __shfl_xor_sync(0xffffffffu, mx0, 1));
        mx0 = fmaxf(mx0, __shfl_xor_sync(0xffffffffu, mx0, 2));
        mx1 = fmaxf(mx1, __shfl_xor_sync(0xffffffffu, mx1, 1));
        mx1 = fmaxf(mx1, __shfl_xor_sync(0xffffffffu, mx1, 2));

        const float mn0 = fmaxf(m0, mx0), mn1 = fmaxf(m1, mx1);
        const float c0f = __expf(m0 - mn0), c1f = __expf(m1 - mn1);
        m0 = mn0; m1 = mn1;

        float ps0 = 0.f, ps1 = 0.f;
#pragma unroll
        for (int ni = 0; ni < 4; ++ni) {
            sacc[ni][0] = __expf(sacc[ni][0] - mn0); ps0 += sacc[ni][0];
            sacc[ni][1] = __expf(sacc[ni][1] - mn0); ps0 += sacc[ni][1];
            sacc[ni][2] = __expf(sacc[ni][2] - mn1); ps1 += sacc[ni][2];
            sacc[ni][3] = __expf(sacc[ni][3] - mn1); ps1 += sacc[ni][3];
        }
        ps0 += __shfl_xor_sync(0xffffffffu, ps0, 1);
        ps0 += __shfl_xor_sync(0xffffffffu, ps0, 2);
        ps1 += __shfl_xor_sync(0xffffffffu, ps1, 1);
        ps1 += __shfl_xor_sync(0xffffffffu, ps1, 2);
        l0 = l0 * c0f + ps0;
        l1 = l1 * c1f + ps1;

#pragma unroll
        for (int ni = 0; ni < 8; ++ni) {
            oacc[ni][0] *= c0f; oacc[ni][1] *= c0f;
            oacc[ni][2] *= c1f; oacc[ni][3] *= c1f;
        }

        // ---- P -> fp16 (1-term), warp-private smem rows ----
#pragma unroll
        for (int ni = 0; ni < 4; ++ni) {
            sPh[rowA * VSTW + ni * 4 + tIG] = pack_h2(sacc[ni][0], sacc[ni][1]);
            sPh[rowB * VSTW + ni * 4 + tIG] = pack_h2(sacc[ni][2], sacc[ni][3]);
        }
        __syncwarp();

        // ---- O += P V (P 1-term, V 2-term) ----
#pragma unroll
        for (int ks = 0; ks < 2; ++ks) {
            unsigned ph[4];
            ph[0] = sPh[rowA * VSTW + ks * 8 + tIG];
            ph[1] = sPh[rowB * VSTW + ks * 8 + tIG];
            ph[2] = sPh[rowA * VSTW + ks * 8 + tIG + 4];
            ph[3] = sPh[rowB * VSTW + ks * 8 + tIG + 4];
#pragma unroll
            for (int ni = 0; ni < 8; ++ni) {
                const int dr = ni * 8 + gID;
                unsigned vh0 = cVh[dr * VSTW + ks * 8 + tIG];
                unsigned vh1 = cVh[dr * VSTW + ks * 8 + tIG + 4];
                unsigned vl0 = cVl[dr * VSTW + ks * 8 + tIG];
                unsigned vl1 = cVl[dr * VSTW + ks * 8 + tIG + 4];
                mma_f16(oacc[ni], ph, vh0, vh1);
                mma_f16(oacc[ni], ph, vl0, vl1);
            }
        }
    }

    // ---- epilogue: normalize + split, write AO hi / lo(x32) words ----
    const float i0 = 1.0f / l0, i1 = 1.0f / l1;
    const size_t oa = (size_t)(b * NN + q0 + rowA) * WPR + h * 32;
    const size_t ob = (size_t)(b * NN + q0 + rowB) * WPR + h * 32;
#pragma unroll
    for (int ni = 0; ni < 8; ++ni) {
        const int w = ni * 4 + tIG;
        float v0 = oacc[ni][0] * i0, v1 = oacc[ni][1] * i0;
        float v2 = oacc[ni][2] * i1, v3 = oacc[ni][3] * i1;
        __half h0 = __float2half_rn(v0), h1 = __float2half_rn(v1);
        __half h2 = __float2half_rn(v2), h3 = __float2half_rn(v3);
        AOh[oa + w] = pack_h2(__half2float(h0), __half2float(h1));
        AOl[oa + w] = pack_h2((v0 - __half2float(h0)) * LOSC,
                              (v1 - __half2float(h1)) * LOSC);
        AOh[ob + w] = pack_h2(__half2float(h2), __half2float(h3));
        AOl[ob + w] = pack_h2((v2 - __half2float(h2)) * LOSC,
                              (v3 - __half2float(h3)) * LOSC);
    }
}

// ============================================================================
// Launch — edge(1), splitX(2), splitW qk(3), splitW vo(4), gemmQKV(5),
// attn(6) <- ncu -s 5 captures this, gemmO(7).
// ============================================================================
extern "C" void kernel_launch(void* const* d_in, const int* in_sizes, int n_in,
                              void* d_out, int out_size)
{
    (void)in_sizes; (void)n_in; (void)out_size;
    const float* x   = (const float*)d_in[0];
    const float* ef  = (const float*)d_in[1];
    const int*   msk = (const int*)  d_in[2];
    const float* Wq  = (const float*)d_in[3];
    const float* bq  = (const float*)d_in[4];
    const float* Wk  = (const float*)d_in[5];
    const float* bk  = (const float*)d_in[6];
    const float* Wv  = (const float*)d_in[7];
    const float* bv  = (const float*)d_in[8];
    const float* We  = (const float*)d_in[9];
    const float* be  = (const float*)d_in[10];
    const float* Wo  = (const float*)d_in[11];
    const float* bo  = (const float*)d_in[12];
    float* out = (float*)d_out;

    unsigned *pxh, *pxl, *pWqh, *pWql, *pWkh, *pWkl, *pWvh, *pWvl, *pWoh, *pWol;
    unsigned *pQh, *pQl, *pKh, *pKl, *pAOh, *pAOl;
    __half *pVth, *pVtl, *pBias;
    cudaGetSymbolAddress((void**)&pxh,  g_xh);  cudaGetSymbolAddress((void**)&pxl,  g_xl);
    cudaGetSymbolAddress((void**)&pWqh, g_Wqh); cudaGetSymbolAddress((void**)&pWql, g_Wql);
    cudaGetSymbolAddress((void**)&pWkh, g_Wkh); cudaGetSymbolAddress((void**)&pWkl, g_Wkl);
    cudaGetSymbolAddress((void**)&pWvh, g_Wvh); cudaGetSymbolAddress((void**)&pWvl, g_Wvl);
    cudaGetSymbolAddress((void**)&pWoh, g_Woh); cudaGetSymbolAddress((void**)&pWol, g_Wol);
    cudaGetSymbolAddress((void**)&pQh,  g_Qh);  cudaGetSymbolAddress((void**)&pQl,  g_Ql);
    cudaGetSymbolAddress((void**)&pKh,  g_Kh);  cudaGetSymbolAddress((void**)&pKl,  g_Kl);
    cudaGetSymbolAddress((void**)&pVth, g_Vth); cudaGetSymbolAddress((void**)&pVtl, g_Vtl);
    cudaGetSymbolAddress((void**)&pAOh, g_AOh); cudaGetSymbolAddress((void**)&pAOl, g_AOl);
    cudaGetSymbolAddress((void**)&pBias, g_bias);

    static cudaStream_t s_edge = nullptr;
    static cudaEvent_t ev_fork = nullptr, ev_join = nullptr;
    if (!s_edge) {
        cudaStreamCreateWithFlags(&s_edge, cudaStreamNonBlocking);
        cudaEventCreateWithFlags(&ev_fork, cudaEventDisableTiming);
        cudaEventCreateWithFlags(&ev_join, cudaEventDisableTiming);
        cudaFuncSetAttribute(gemm_f16, cudaFuncAttributeMaxDynamicSharedMemorySize,
                             GEMM_SMEM);
        cudaFuncSetAttribute(attn_f16, cudaFuncAttributeMaxDynamicSharedMemorySize,
                             ATTN_SMEM);
    }

    // ---- fork: edge bias (pure DRAM) concurrent with splits + QKV ----
    cudaEventRecord(ev_fork, 0);
    cudaStreamWaitEvent(s_edge, ev_fork, 0);
    edge_bias_kernel<<<(BB * NN * NN) / 256, 256, 0, s_edge>>>(
        (const float4*)ef, msk, We, be, pBias);
    cudaEventRecord(ev_join, s_edge);

    // ---- main chain: splits -> QKV ----
    split_kernel<<<(MM * FF / 4) / 256, 256>>>((const float4*)x,  (uint2*)pxh,  (uint2*)pxl);
    dim3 gs((FF * FF / 4) / 256, 2);
    split2_kernel<<<gs, 256>>>((const float4*)Wq, (uint2*)pWqh, (uint2*)pWql,
                               (const float4*)Wk, (uint2*)pWkh, (uint2*)pWkl);
    split2_kernel<<<gs, 256>>>((const float4*)Wv, (uint2*)pWvh, (uint2*)pWvl,
                               (const float4*)Wo, (uint2*)pWoh, (uint2*)pWol);

    dim3 gqkv(512 / 64, MM / 128, 3);
    gemm_f16<<<gqkv, 256, GEMM_SMEM>>>(pxh, pxl,
                            pWqh, pWql, pWkh, pWkl, pWvh, pWvl,
                            bq, bk, bv,
                            nullptr, pQh, pQl, pKh, pKl, pVth, pVtl, 0);

    cudaStreamWaitEvent(0, ev_join, 0);

    attn_f16<<<dim3(NN / 64, HH, BB), 128, ATTN_SMEM>>>(
        pQh, pQl, pKh, pKl, pVth, pVtl, pBias, pAOh, pAOl);

    dim3 go(512 / 64, MM / 128, 1);
    gemm_f16<<<go, 256, GEMM_SMEM>>>(pAOh, pAOl,
                          pWoh, pWol, pWoh, pWol, pWoh, pWol,
                          bo, bo, bo,
                          out, nullptr, nullptr, nullptr, nullptr,
                          nullptr, nullptr, 1);
}